// round 8
// baseline (speedup 1.0000x reference)
#include <cuda_runtime.h>
#include <cuda_bf16.h>
#include <math.h>
#include <stdint.h>

#define Bb 8
#define Cc 256
#define Nn 2304
#define BM 64
#define BN 128
#define KT (Nn / BN)      // 18
#define SHIFT 30.0f

// ---------------- bf16 hi/lo global scratch ----------------
__device__ __align__(16) unsigned short g_Qh[(size_t)Bb * Nn * Cc];
__device__ __align__(16) unsigned short g_Ql[(size_t)Bb * Nn * Cc];
__device__ __align__(16) unsigned short g_Kh[(size_t)Bb * Nn * Cc];
__device__ __align__(16) unsigned short g_Kl[(size_t)Bb * Nn * Cc];
__device__ __align__(16) unsigned short g_Vth[(size_t)Bb * Cc * Nn];
__device__ __align__(16) unsigned short g_Vtl[(size_t)Bb * Cc * Nn];
// inputs split to bf16 hi/lo (channel-major, same layout as x/y)
__device__ __align__(16) unsigned short g_Xh[(size_t)Bb * Cc * Nn];
__device__ __align__(16) unsigned short g_Xl[(size_t)Bb * Cc * Nn];
__device__ __align__(16) unsigned short g_Yh[(size_t)Bb * Cc * Nn];
__device__ __align__(16) unsigned short g_Yl[(size_t)Bb * Cc * Nn];
// weights split ([co][ci], row-major)
__device__ __align__(16) unsigned short g_Wh[3][Cc * Cc];
__device__ __align__(16) unsigned short g_Wl[3][Cc * Cc];

// ---------------- helpers ----------------
__device__ __forceinline__ uint32_t smem_u32(const void* p) {
    uint32_t a;
    asm("{ .reg .u64 t; cvta.to.shared.u64 t, %1; cvt.u32.u64 %0, t; }" : "=r"(a) : "l"(p));
    return a;
}

#define LDSM4(r, addr) \
    asm volatile("ldmatrix.sync.aligned.m8n8.x4.shared.b16 {%0,%1,%2,%3}, [%4];" \
        : "=r"((r)[0]), "=r"((r)[1]), "=r"((r)[2]), "=r"((r)[3]) : "r"(addr))
#define LDSM4T(r, addr) \
    asm volatile("ldmatrix.sync.aligned.m8n8.x4.trans.shared.b16 {%0,%1,%2,%3}, [%4];" \
        : "=r"((r)[0]), "=r"((r)[1]), "=r"((r)[2]), "=r"((r)[3]) : "r"(addr))

__device__ __forceinline__ void mma_bf16(float* c, const uint32_t* a,
                                         uint32_t b0, uint32_t b1) {
    asm volatile(
        "mma.sync.aligned.m16n8k16.row.col.f32.bf16.bf16.f32 "
        "{%0,%1,%2,%3}, {%4,%5,%6,%7}, {%8,%9}, {%0,%1,%2,%3};"
        : "+f"(c[0]), "+f"(c[1]), "+f"(c[2]), "+f"(c[3])
        : "r"(a[0]), "r"(a[1]), "r"(a[2]), "r"(a[3]), "r"(b0), "r"(b1));
}

__device__ __forceinline__ void cp16(uint32_t s, const void* g) {
    asm volatile("cp.async.cg.shared.global [%0], [%1], 16;" :: "r"(s), "l"(g) : "memory");
}
#define CP_COMMIT() asm volatile("cp.async.commit_group;" ::: "memory")
#define CP_WAIT0()  asm volatile("cp.async.wait_group 0;" ::: "memory")

__device__ __forceinline__ void split2(float v, unsigned short& h, unsigned short& l) {
    __nv_bfloat16 bh = __float2bfloat16(v);
    float r = v - __bfloat162float(bh);
    h = __bfloat16_as_ushort(bh);
    l = __bfloat16_as_ushort(__float2bfloat16(r));
}

__device__ __forceinline__ void split_pack(float a, float b, uint32_t& h, uint32_t& l) {
    unsigned short ah, al, bh, bl;
    split2(a, ah, al);
    split2(b, bh, bl);
    h = (uint32_t)ah | ((uint32_t)bh << 16);
    l = (uint32_t)al | ((uint32_t)bl << 16);
}

// ---------------------------------------------------------------------------
// Prep: split x,y (fp32) -> bf16 hi/lo, same layout. grid (2304,1,2) x 256
// ---------------------------------------------------------------------------
__global__ __launch_bounds__(256) void prep_xy(const float4* __restrict__ x,
                                               const float4* __restrict__ y)
{
    const int z = blockIdx.z;
    const float4* src = z ? y : x;
    uint4* H = (uint4*)(z ? g_Yh : g_Xh);
    uint4* L = (uint4*)(z ? g_Yl : g_Xl);
    size_t i = (size_t)blockIdx.x * 512 + threadIdx.x * 2;
    float4 f0 = src[i], f1 = src[i + 1];
    uint4 h, l;
    split_pack(f0.x, f0.y, h.x, l.x);
    split_pack(f0.z, f0.w, h.y, l.y);
    split_pack(f1.x, f1.y, h.z, l.z);
    split_pack(f1.z, f1.w, h.w, l.w);
    H[i >> 1] = h;
    L[i >> 1] = l;
}

// Prep: split Wq/Wk/Wv. grid (64,1,3) x 256
__global__ __launch_bounds__(256) void prep_w(const float4* __restrict__ Wq,
                                              const float4* __restrict__ Wk,
                                              const float4* __restrict__ Wv)
{
    const int z = blockIdx.z;
    const float4* src = (z == 0) ? Wq : ((z == 1) ? Wk : Wv);
    uint2* H = (uint2*)g_Wh[z];
    uint2* L = (uint2*)g_Wl[z];
    int i = blockIdx.x * 256 + threadIdx.x;
    float4 f = src[i];
    uint2 h, l;
    split_pack(f.x, f.y, h.x, l.x);
    split_pack(f.z, f.w, h.y, l.y);
    H[i] = h;
    L[i] = l;
}

// ---------------------------------------------------------------------------
// HMMA projections (bf16x3): 64tok x 64co per CTA, 128 threads (4 warps).
// ---------------------------------------------------------------------------
#define PX_H 0
#define PX_L 9216
#define PW_H 18432
#define PW_L 27648

__global__ __launch_bounds__(128) void proj_hmma(
    const float* __restrict__ bq, const float* __restrict__ bk,
    const float* __restrict__ bv)
{
    __shared__ char psm[36864];
    const uint32_t sb = smem_u32(psm);

    const int tid  = threadIdx.x;
    const int wid  = tid >> 5;
    const int lane = tid & 31;
    const int n0    = blockIdx.x * 64;
    const int co0   = blockIdx.y * 64;
    const int which = blockIdx.z >> 3;
    const int b     = blockIdx.z & 7;

    const unsigned short* Xh = (which == 0) ? g_Xh : g_Yh;
    const unsigned short* Xl = (which == 0) ? g_Xl : g_Yl;
    const unsigned short* Wh = g_Wh[which];
    const unsigned short* Wl = g_Wl[which];
    const float* bias = (which == 0) ? bq : ((which == 1) ? bk : bv);

    const int a_ci = (lane & 7) + ((lane >> 4) & 1) * 8;
    const int a_m  = wid * 16 + ((lane >> 3) & 1) * 8;
    const int b_row = (lane & 7) + (lane >> 4) * 8;
    const int b_k   = ((lane >> 3) & 1) * 8;

    float acc[8][4];
#pragma unroll
    for (int j = 0; j < 8; j++)
#pragma unroll
        for (int e = 0; e < 4; e++) acc[j][e] = 0.f;

    for (int ck = 0; ck < 4; ++ck) {
#pragma unroll
        for (int t = 0; t < 4; ++t) {
            int l = tid + t * 128;
            int r = l >> 3, s = l & 7;
            size_t xg = (((size_t)b * Cc + ck * 64 + r) * Nn + n0 + s * 8) * 2;
            uint32_t xo = (uint32_t)(r * 144 + s * 16);
            cp16(sb + PX_H + xo, (const char*)Xh + xg);
            cp16(sb + PX_L + xo, (const char*)Xl + xg);
            size_t wg = (size_t)((co0 + r) * Cc + ck * 64 + s * 8) * 2;
            cp16(sb + PW_H + xo, (const char*)Wh + wg);
            cp16(sb + PW_L + xo, (const char*)Wl + wg);
        }
        CP_COMMIT();
        CP_WAIT0();
        __syncthreads();

#pragma unroll
        for (int ks = 0; ks < 4; ++ks) {
            uint32_t ah[4], al4[4];
            uint32_t aa = (uint32_t)((ks * 16 + a_ci) * 144 + a_m * 2);
            LDSM4T(ah, sb + PX_H + aa);
            LDSM4T(al4, sb + PX_L + aa);
            uint32_t BH[4][4], BL[4][4];
#pragma unroll
            for (int nb = 0; nb < 4; ++nb) {
                uint32_t ba = (uint32_t)((nb * 16 + b_row) * 144 + (ks * 16 + b_k) * 2);
                LDSM4(BH[nb], sb + PW_H + ba);
                LDSM4(BL[nb], sb + PW_L + ba);
            }
#pragma unroll
            for (int nb = 0; nb < 4; ++nb) {
                mma_bf16(acc[2 * nb],     ah, BH[nb][0], BH[nb][1]);
                mma_bf16(acc[2 * nb + 1], ah, BH[nb][2], BH[nb][3]);
            }
#pragma unroll
            for (int nb = 0; nb < 4; ++nb) {
                mma_bf16(acc[2 * nb],     al4, BH[nb][0], BH[nb][1]);
                mma_bf16(acc[2 * nb + 1], al4, BH[nb][2], BH[nb][3]);
            }
#pragma unroll
            for (int nb = 0; nb < 4; ++nb) {
                mma_bf16(acc[2 * nb],     ah, BL[nb][0], BL[nb][1]);
                mma_bf16(acc[2 * nb + 1], ah, BL[nb][2], BL[nb][3]);
            }
        }
        __syncthreads();
    }

    const int m1 = wid * 16 + (lane >> 2);

    if (which < 2) {
        unsigned short* Gh = which ? g_Kh : g_Qh;
        unsigned short* Gl = which ? g_Kl : g_Ql;
#pragma unroll
        for (int j = 0; j < 8; ++j) {
            int co = j * 8 + (lane & 3) * 2;
            float b0 = bias[co0 + co], b1 = bias[co0 + co + 1];
            uint32_t h01, l01, h23, l23;
            split_pack(acc[j][0] + b0, acc[j][1] + b1, h01, l01);
            split_pack(acc[j][2] + b0, acc[j][3] + b1, h23, l23);
            size_t e1 = ((size_t)b * Nn + n0 + m1) * Cc + co0 + co;
            size_t e2 = e1 + 8 * (size_t)Cc;
            *(uint32_t*)(Gh + e1) = h01;
            *(uint32_t*)(Gl + e1) = l01;
            *(uint32_t*)(Gh + e2) = h23;
            *(uint32_t*)(Gl + e2) = l23;
        }
    } else {
        float* stage = (float*)psm;     // [co 64][m 68]
#pragma unroll
        for (int j = 0; j < 8; ++j) {
            int co = j * 8 + (lane & 3) * 2;
            float b0 = bias[co0 + co], b1 = bias[co0 + co + 1];
            stage[co * 68 + m1]           = acc[j][0] + b0;
            stage[(co + 1) * 68 + m1]     = acc[j][1] + b1;
            stage[co * 68 + m1 + 8]       = acc[j][2] + b0;
            stage[(co + 1) * 68 + m1 + 8] = acc[j][3] + b1;
        }
        __syncthreads();
#pragma unroll
        for (int l = tid; l < 2048; l += 128) {
            int co = l >> 5, mp = (l & 31) * 2;
            float v0 = stage[co * 68 + mp], v1 = stage[co * 68 + mp + 1];
            uint32_t h, lo;
            split_pack(v0, v1, h, lo);
            size_t e = ((size_t)b * Cc + co0 + co) * Nn + n0 + mp;
            *(uint32_t*)(g_Vth + e) = h;
            *(uint32_t*)(g_Vtl + e) = lo;
        }
    }
}

// ---------------------------------------------------------------------------
// HMMA flash attention: 512 threads (16 warps, 4/SMSP) for LDSM/MMA overlap.
// Warp tile: S = 16 rows x 32 cols (wm = wid&3, wn = wid>>2),
//            PV = 16 rows x 16 ch per chunk.
// Pipeline: 1 sync/chunk, double-buffered cp.async. pitches (b16): Q 264,
// K 72, V/P 136.
// ---------------------------------------------------------------------------
#define SM_RS  0
#define SM_QH  256
#define SM_QL  (SM_QH + 33792)            // 34048
#define SM_B0H (SM_QL + 33792)            // 67840
#define SM_B0L (SM_B0H + 18432)           // 86272
#define SM_B1H (SM_B0L + 18432)           // 104704
#define SM_B1L (SM_B1H + 18432)           // 123136
#define SM_PH  (SM_B1L + 18432)           // 141568
#define SM_PL  (SM_PH + 17408)            // 158976
#define ATTN_SMEM (SM_PL + 17408)         // 176384

__global__ __launch_bounds__(512, 1) void attn_kernel(float* __restrict__ out)
{
    extern __shared__ char smem[];
    float* rs = (float*)(smem + SM_RS);
    const uint32_t sbase = smem_u32(smem);

    const int tid  = threadIdx.x;
    const int wid  = tid >> 5;
    const int lane = tid & 31;
    const int b    = blockIdx.y;
    const int m0   = blockIdx.x * BM;

    const int wm = (wid & 3) * 16;    // warp row block (4 groups of 16)
    const int wn = wid >> 2;          // col quarter (S: 32 cols) / ch slice (PV: 16)

    const int arow   = wm + (lane & 7) + ((lane >> 3) & 1) * 8;
    const int ak     = (lane >> 4) * 8;
    const int bn_row = (lane & 7) + (lane >> 4) * 8;
    const int bk_add = ((lane >> 3) & 1) * 8;

    const uint32_t qbH = sbase + SM_QH, qbL = sbase + SM_QL;
    const uint32_t pbH = sbase + SM_PH, pbL = sbase + SM_PL;

    if (tid < 64) rs[tid] = 0.f;

    {
        const uint4* Gh = (const uint4*)g_Qh;
        const uint4* Gl = (const uint4*)g_Ql;
        uint4* Dh = (uint4*)(smem + SM_QH);
        uint4* Dl = (uint4*)(smem + SM_QL);
#pragma unroll
        for (int l = tid; l < 2048; l += 512) {
            int m = l >> 5, c8 = l & 31;
            size_t gi = (((size_t)b * Nn + m0 + m) * Cc + c8 * 8) >> 3;
            int d = m * 33 + c8;
            Dh[d] = Gh[gi];
            Dl[d] = Gl[gi];
        }
    }

    auto issue_chunk = [&](int ci) {
        int kt2 = ci >> 3, j2 = ci & 7, n02 = kt2 * BN;
        uint32_t bH = sbase + ((ci & 1) ? SM_B1H : SM_B0H);
        uint32_t bL = sbase + ((ci & 1) ? SM_B1L : SM_B0L);
        if (j2 < 4) {
            const char* Gh = (const char*)g_Kh;
            const char* Gl = (const char*)g_Kl;
#pragma unroll
            for (int t = 0; t < 2; ++t) {
                int l = tid + t * 512;
                int n = l >> 3, c8 = l & 7;
                size_t gb = (((size_t)b * Nn + n02 + n) * Cc + j2 * 64 + c8 * 8) * 2;
                uint32_t so = (uint32_t)((n * 72 + c8 * 8) * 2);
                cp16(bH + so, Gh + gb);
                cp16(bL + so, Gl + gb);
            }
        } else {
            int vc = j2 - 4;
            const char* Gh = (const char*)g_Vth;
            const char* Gl = (const char*)g_Vtl;
#pragma unroll
            for (int t = 0; t < 2; ++t) {
                int l = tid + t * 512;
                int c = l >> 4, j8 = l & 15;
                size_t gb = (((size_t)b * Cc + vc * 64 + c) * Nn + n02 + j8 * 8) * 2;
                uint32_t so = (uint32_t)((c * 136 + j8 * 8) * 2);
                cp16(bH + so, Gh + gb);
                cp16(bL + so, Gl + gb);
            }
        }
    };

    float oacc[8][4];
#pragma unroll
    for (int f = 0; f < 8; f++)
#pragma unroll
        for (int e = 0; e < 4; e++) oacc[f][e] = 0.f;

    float sacc[4][4];
    float s0 = 0.f, s1 = 0.f;

    issue_chunk(0);
    CP_COMMIT();

    for (int kt = 0; kt < KT; ++kt) {
        for (int j = 0; j < 8; ++j) {
            const int i = kt * 8 + j;
            CP_WAIT0();
            __syncthreads();
            if (i + 1 < KT * 8) issue_chunk(i + 1);
            CP_COMMIT();

            const uint32_t bH = sbase + ((i & 1) ? SM_B1H : SM_B0H);
            const uint32_t bL = sbase + ((i & 1) ? SM_B1L : SM_B0L);

            if (j < 4) {
                // ------------- S += Q K^T (channel chunk j) -------------
                const int cc = j;
                if (j == 0) {
#pragma unroll
                    for (int f = 0; f < 4; f++)
#pragma unroll
                        for (int e = 0; e < 4; e++) sacc[f][e] = 0.f;
                }
#pragma unroll
                for (int ks = 0; ks < 4; ++ks) {
                    const int k0 = ks * 16;
                    uint32_t qh[4], ql[4];
                    uint32_t qa = (uint32_t)((arow * 264 + cc * 64 + k0 + ak) * 2);
                    LDSM4(qh, qbH + qa);
                    LDSM4(ql, qbL + qa);
                    uint32_t BH[2][4], BL[2][4];
#pragma unroll
                    for (int nb = 0; nb < 2; ++nb) {
                        uint32_t kaddr = (uint32_t)(((wn * 32 + nb * 16 + bn_row) * 72 + k0 + bk_add) * 2);
                        LDSM4(BH[nb], bH + kaddr);
                        LDSM4(BL[nb], bL + kaddr);
                    }
                    mma_bf16(sacc[0], qh, BH[0][0], BH[0][1]);
                    mma_bf16(sacc[1], qh, BH[0][2], BH[0][3]);
                    mma_bf16(sacc[2], qh, BH[1][0], BH[1][1]);
                    mma_bf16(sacc[3], qh, BH[1][2], BH[1][3]);
                    mma_bf16(sacc[0], ql, BH[0][0], BH[0][1]);
                    mma_bf16(sacc[1], ql, BH[0][2], BH[0][3]);
                    mma_bf16(sacc[2], ql, BH[1][0], BH[1][1]);
                    mma_bf16(sacc[3], ql, BH[1][2], BH[1][3]);
                    mma_bf16(sacc[0], qh, BL[0][0], BL[0][1]);
                    mma_bf16(sacc[1], qh, BL[0][2], BL[0][3]);
                    mma_bf16(sacc[2], qh, BL[1][0], BL[1][1]);
                    mma_bf16(sacc[3], qh, BL[1][2], BL[1][3]);
                }
                if (j == 3) {
                    const int row = wm + (lane >> 2);
#pragma unroll
                    for (int f = 0; f < 4; ++f) {
                        float p0 = __expf(sacc[f][0] - SHIFT);
                        float p1 = __expf(sacc[f][1] - SHIFT);
                        float p2 = __expf(sacc[f][2] - SHIFT);
                        float p3 = __expf(sacc[f][3] - SHIFT);
                        s0 += p0 + p1;
                        s1 += p2 + p3;
                        int col = wn * 32 + f * 8 + (lane & 3) * 2;
                        uint32_t h01, l01, h23, l23;
                        split_pack(p0, p1, h01, l01);
                        split_pack(p2, p3, h23, l23);
                        *(uint32_t*)(smem + SM_PH + (row * 136 + col) * 2)       = h01;
                        *(uint32_t*)(smem + SM_PL + (row * 136 + col) * 2)       = l01;
                        *(uint32_t*)(smem + SM_PH + ((row + 8) * 136 + col) * 2) = h23;
                        *(uint32_t*)(smem + SM_PL + ((row + 8) * 136 + col) * 2) = l23;
                    }
                }
            } else {
                // ------------- O += P V (channel chunk j-4, 16 ch/warp) -------------
                const int vc = j - 4;
                float* o0 = oacc[vc * 2];
                float* o1 = oacc[vc * 2 + 1];
#pragma unroll
                for (int ks = 0; ks < 8; ++ks) {
                    const int k0 = ks * 16;
                    uint32_t ph[4], pl[4];
                    uint32_t pa = (uint32_t)((arow * 136 + k0 + ak) * 2);
                    LDSM4(ph, pbH + pa);
                    LDSM4(pl, pbL + pa);
                    uint32_t VH[4], VL[4];
                    uint32_t va = (uint32_t)(((wn * 16 + bn_row) * 136 + k0 + bk_add) * 2);
                    LDSM4(VH, bH + va);
                    LDSM4(VL, bL + va);
                    mma_bf16(o0, ph, VH[0], VH[1]);
                    mma_bf16(o1, ph, VH[2], VH[3]);
                    mma_bf16(o0, pl, VH[0], VH[1]);
                    mma_bf16(o1, pl, VH[2], VH[3]);
                    mma_bf16(o0, ph, VL[0], VL[1]);
                    mma_bf16(o1, ph, VL[2], VL[3]);
                }
            }
        }
    }

    __syncthreads();
    atomicAdd(&rs[wm + (lane >> 2)], s0);
    atomicAdd(&rs[wm + (lane >> 2) + 8], s1);
    __syncthreads();
    if (tid < 64) rs[tid] = 1.f / rs[tid];
    __syncthreads();

    float* stage = (float*)(smem + SM_QH);   // 128 x 68 f32 (reuse Q area)
    float* outb = out + (size_t)b * Cc * Nn;
    const int row = wm + (lane >> 2);

#pragma unroll
    for (int p = 0; p < 2; ++p) {
#pragma unroll
        for (int v2 = 0; v2 < 2; ++v2) {
            int vc = p * 2 + v2;
#pragma unroll
            for (int h = 0; h < 2; ++h) {
                int f = vc * 2 + h;
                int ch = v2 * 64 + wn * 16 + h * 8 + (lane & 3) * 2;  // within 128-pass
                stage[(ch)     * 68 + row]     = oacc[f][0];
                stage[(ch + 1) * 68 + row]     = oacc[f][1];
                stage[(ch)     * 68 + row + 8] = oacc[f][2];
                stage[(ch + 1) * 68 + row + 8] = oacc[f][3];
            }
        }
        __syncthreads();
#pragma unroll
        for (int l = tid; l < 8192; l += 512) {
            int r = l >> 6, m = l & 63;
            outb[(size_t)(p * 128 + r) * Nn + m0 + m] = stage[r * 68 + m] * rs[m];
        }
        __syncthreads();
    }
}

// ---------------------------------------------------------------------------
extern "C" void kernel_launch(void* const* d_in, const int* in_sizes, int n_in,
                              void* d_out, int out_size)
{
    (void)in_sizes; (void)n_in; (void)out_size;
    const float* x  = (const float*)d_in[0];
    const float* y  = (const float*)d_in[1];
    const float* Wq = (const float*)d_in[2];
    const float* bq = (const float*)d_in[3];
    const float* Wk = (const float*)d_in[4];
    const float* bk = (const float*)d_in[5];
    const float* Wv = (const float*)d_in[6];
    const float* bv = (const float*)d_in[7];
    float* out = (float*)d_out;

    prep_xy<<<dim3(2304, 1, 2), 256>>>((const float4*)x, (const float4*)y);
    prep_w<<<dim3(64, 1, 3), 256>>>((const float4*)Wq, (const float4*)Wk,
                                    (const float4*)Wv);
    proj_hmma<<<dim3(Nn / 64, Cc / 64, 24), 128>>>(bq, bk, bv);

    cudaFuncSetAttribute(attn_kernel,
                         cudaFuncAttributeMaxDynamicSharedMemorySize, ATTN_SMEM);
    dim3 ag(Nn / BM, Bb);
    attn_kernel<<<ag, 512, ATTN_SMEM>>>(out);
}

// round 9
// speedup vs baseline: 1.0207x; 1.0207x over previous
#include <cuda_runtime.h>
#include <cuda_bf16.h>
#include <math.h>
#include <stdint.h>

#define Bb 8
#define Cc 256
#define Nn 2304
#define BM 64
#define BN 128
#define KT (Nn / BN)      // 18
#define SHIFT 30.0f

// ---------------- bf16 hi/lo global scratch ----------------
__device__ __align__(16) unsigned short g_Qh[(size_t)Bb * Nn * Cc];
__device__ __align__(16) unsigned short g_Ql[(size_t)Bb * Nn * Cc];
__device__ __align__(16) unsigned short g_Kh[(size_t)Bb * Nn * Cc];
__device__ __align__(16) unsigned short g_Kl[(size_t)Bb * Nn * Cc];
__device__ __align__(16) unsigned short g_Vth[(size_t)Bb * Cc * Nn];
__device__ __align__(16) unsigned short g_Vtl[(size_t)Bb * Cc * Nn];
// inputs split to bf16 hi/lo (channel-major, same layout as x/y)
__device__ __align__(16) unsigned short g_Xh[(size_t)Bb * Cc * Nn];
__device__ __align__(16) unsigned short g_Xl[(size_t)Bb * Cc * Nn];
__device__ __align__(16) unsigned short g_Yh[(size_t)Bb * Cc * Nn];
__device__ __align__(16) unsigned short g_Yl[(size_t)Bb * Cc * Nn];
// weights split ([co][ci], row-major)
__device__ __align__(16) unsigned short g_Wh[3][Cc * Cc];
__device__ __align__(16) unsigned short g_Wl[3][Cc * Cc];

// ---------------- helpers ----------------
__device__ __forceinline__ uint32_t smem_u32(const void* p) {
    uint32_t a;
    asm("{ .reg .u64 t; cvta.to.shared.u64 t, %1; cvt.u32.u64 %0, t; }" : "=r"(a) : "l"(p));
    return a;
}

#define LDSM4(r, addr) \
    asm volatile("ldmatrix.sync.aligned.m8n8.x4.shared.b16 {%0,%1,%2,%3}, [%4];" \
        : "=r"((r)[0]), "=r"((r)[1]), "=r"((r)[2]), "=r"((r)[3]) : "r"(addr))
#define LDSM4T(r, addr) \
    asm volatile("ldmatrix.sync.aligned.m8n8.x4.trans.shared.b16 {%0,%1,%2,%3}, [%4];" \
        : "=r"((r)[0]), "=r"((r)[1]), "=r"((r)[2]), "=r"((r)[3]) : "r"(addr))

__device__ __forceinline__ void mma_bf16(float* c, const uint32_t* a,
                                         uint32_t b0, uint32_t b1) {
    asm volatile(
        "mma.sync.aligned.m16n8k16.row.col.f32.bf16.bf16.f32 "
        "{%0,%1,%2,%3}, {%4,%5,%6,%7}, {%8,%9}, {%0,%1,%2,%3};"
        : "+f"(c[0]), "+f"(c[1]), "+f"(c[2]), "+f"(c[3])
        : "r"(a[0]), "r"(a[1]), "r"(a[2]), "r"(a[3]), "r"(b0), "r"(b1));
}

__device__ __forceinline__ void cp16(uint32_t s, const void* g) {
    asm volatile("cp.async.cg.shared.global [%0], [%1], 16;" :: "r"(s), "l"(g) : "memory");
}
#define CP_COMMIT() asm volatile("cp.async.commit_group;" ::: "memory")
#define CP_WAIT0()  asm volatile("cp.async.wait_group 0;" ::: "memory")

__device__ __forceinline__ void split2(float v, unsigned short& h, unsigned short& l) {
    __nv_bfloat16 bh = __float2bfloat16(v);
    float r = v - __bfloat162float(bh);
    h = __bfloat16_as_ushort(bh);
    l = __bfloat16_as_ushort(__float2bfloat16(r));
}

__device__ __forceinline__ void split_pack(float a, float b, uint32_t& h, uint32_t& l) {
    unsigned short ah, al, bh, bl;
    split2(a, ah, al);
    split2(b, bh, bl);
    h = (uint32_t)ah | ((uint32_t)bh << 16);
    l = (uint32_t)al | ((uint32_t)bl << 16);
}

// ---------------------------------------------------------------------------
// Prep: split x,y (fp32) -> bf16 hi/lo, same layout. grid (2304,1,2) x 256
// ---------------------------------------------------------------------------
__global__ __launch_bounds__(256) void prep_xy(const float4* __restrict__ x,
                                               const float4* __restrict__ y)
{
    const int z = blockIdx.z;
    const float4* src = z ? y : x;
    uint4* H = (uint4*)(z ? g_Yh : g_Xh);
    uint4* L = (uint4*)(z ? g_Yl : g_Xl);
    size_t i = (size_t)blockIdx.x * 512 + threadIdx.x * 2;
    float4 f0 = src[i], f1 = src[i + 1];
    uint4 h, l;
    split_pack(f0.x, f0.y, h.x, l.x);
    split_pack(f0.z, f0.w, h.y, l.y);
    split_pack(f1.x, f1.y, h.z, l.z);
    split_pack(f1.z, f1.w, h.w, l.w);
    H[i >> 1] = h;
    L[i >> 1] = l;
}

// Prep: split Wq/Wk/Wv. grid (64,1,3) x 256
__global__ __launch_bounds__(256) void prep_w(const float4* __restrict__ Wq,
                                              const float4* __restrict__ Wk,
                                              const float4* __restrict__ Wv)
{
    const int z = blockIdx.z;
    const float4* src = (z == 0) ? Wq : ((z == 1) ? Wk : Wv);
    uint2* H = (uint2*)g_Wh[z];
    uint2* L = (uint2*)g_Wl[z];
    int i = blockIdx.x * 256 + threadIdx.x;
    float4 f = src[i];
    uint2 h, l;
    split_pack(f.x, f.y, h.x, l.x);
    split_pack(f.z, f.w, h.y, l.y);
    H[i] = h;
    L[i] = l;
}

// ---------------------------------------------------------------------------
// HMMA projections (bf16x3): 64tok x 64co per CTA, 128 threads (4 warps).
// ---------------------------------------------------------------------------
#define PX_H 0
#define PX_L 9216
#define PW_H 18432
#define PW_L 27648

__global__ __launch_bounds__(128) void proj_hmma(
    const float* __restrict__ bq, const float* __restrict__ bk,
    const float* __restrict__ bv)
{
    __shared__ char psm[36864];
    const uint32_t sb = smem_u32(psm);

    const int tid  = threadIdx.x;
    const int wid  = tid >> 5;
    const int lane = tid & 31;
    const int n0    = blockIdx.x * 64;
    const int co0   = blockIdx.y * 64;
    const int which = blockIdx.z >> 3;
    const int b     = blockIdx.z & 7;

    const unsigned short* Xh = (which == 0) ? g_Xh : g_Yh;
    const unsigned short* Xl = (which == 0) ? g_Xl : g_Yl;
    const unsigned short* Wh = g_Wh[which];
    const unsigned short* Wl = g_Wl[which];
    const float* bias = (which == 0) ? bq : ((which == 1) ? bk : bv);

    const int a_ci = (lane & 7) + ((lane >> 4) & 1) * 8;
    const int a_m  = wid * 16 + ((lane >> 3) & 1) * 8;
    const int b_row = (lane & 7) + (lane >> 4) * 8;
    const int b_k   = ((lane >> 3) & 1) * 8;

    float acc[8][4];
#pragma unroll
    for (int j = 0; j < 8; j++)
#pragma unroll
        for (int e = 0; e < 4; e++) acc[j][e] = 0.f;

    for (int ck = 0; ck < 4; ++ck) {
#pragma unroll
        for (int t = 0; t < 4; ++t) {
            int l = tid + t * 128;
            int r = l >> 3, s = l & 7;
            size_t xg = (((size_t)b * Cc + ck * 64 + r) * Nn + n0 + s * 8) * 2;
            uint32_t xo = (uint32_t)(r * 144 + s * 16);
            cp16(sb + PX_H + xo, (const char*)Xh + xg);
            cp16(sb + PX_L + xo, (const char*)Xl + xg);
            size_t wg = (size_t)((co0 + r) * Cc + ck * 64 + s * 8) * 2;
            cp16(sb + PW_H + xo, (const char*)Wh + wg);
            cp16(sb + PW_L + xo, (const char*)Wl + wg);
        }
        CP_COMMIT();
        CP_WAIT0();
        __syncthreads();

#pragma unroll
        for (int ks = 0; ks < 4; ++ks) {
            uint32_t ah[4], al4[4];
            uint32_t aa = (uint32_t)((ks * 16 + a_ci) * 144 + a_m * 2);
            LDSM4T(ah, sb + PX_H + aa);
            LDSM4T(al4, sb + PX_L + aa);
            uint32_t BH[4][4], BL[4][4];
#pragma unroll
            for (int nb = 0; nb < 4; ++nb) {
                uint32_t ba = (uint32_t)((nb * 16 + b_row) * 144 + (ks * 16 + b_k) * 2);
                LDSM4(BH[nb], sb + PW_H + ba);
                LDSM4(BL[nb], sb + PW_L + ba);
            }
#pragma unroll
            for (int nb = 0; nb < 4; ++nb) {
                mma_bf16(acc[2 * nb],     ah, BH[nb][0], BH[nb][1]);
                mma_bf16(acc[2 * nb + 1], ah, BH[nb][2], BH[nb][3]);
            }
#pragma unroll
            for (int nb = 0; nb < 4; ++nb) {
                mma_bf16(acc[2 * nb],     al4, BH[nb][0], BH[nb][1]);
                mma_bf16(acc[2 * nb + 1], al4, BH[nb][2], BH[nb][3]);
            }
#pragma unroll
            for (int nb = 0; nb < 4; ++nb) {
                mma_bf16(acc[2 * nb],     ah, BL[nb][0], BL[nb][1]);
                mma_bf16(acc[2 * nb + 1], ah, BL[nb][2], BL[nb][3]);
            }
        }
        __syncthreads();
    }

    const int m1 = wid * 16 + (lane >> 2);

    if (which < 2) {
        unsigned short* Gh = which ? g_Kh : g_Qh;
        unsigned short* Gl = which ? g_Kl : g_Ql;
#pragma unroll
        for (int j = 0; j < 8; ++j) {
            int co = j * 8 + (lane & 3) * 2;
            float b0 = bias[co0 + co], b1 = bias[co0 + co + 1];
            uint32_t h01, l01, h23, l23;
            split_pack(acc[j][0] + b0, acc[j][1] + b1, h01, l01);
            split_pack(acc[j][2] + b0, acc[j][3] + b1, h23, l23);
            size_t e1 = ((size_t)b * Nn + n0 + m1) * Cc + co0 + co;
            size_t e2 = e1 + 8 * (size_t)Cc;
            *(uint32_t*)(Gh + e1) = h01;
            *(uint32_t*)(Gl + e1) = l01;
            *(uint32_t*)(Gh + e2) = h23;
            *(uint32_t*)(Gl + e2) = l23;
        }
    } else {
        float* stage = (float*)psm;     // [co 64][m 68]
#pragma unroll
        for (int j = 0; j < 8; ++j) {
            int co = j * 8 + (lane & 3) * 2;
            float b0 = bias[co0 + co], b1 = bias[co0 + co + 1];
            stage[co * 68 + m1]           = acc[j][0] + b0;
            stage[(co + 1) * 68 + m1]     = acc[j][1] + b1;
            stage[co * 68 + m1 + 8]       = acc[j][2] + b0;
            stage[(co + 1) * 68 + m1 + 8] = acc[j][3] + b1;
        }
        __syncthreads();
#pragma unroll
        for (int l = tid; l < 2048; l += 128) {
            int co = l >> 5, mp = (l & 31) * 2;
            float v0 = stage[co * 68 + mp], v1 = stage[co * 68 + mp + 1];
            uint32_t h, lo;
            split_pack(v0, v1, h, lo);
            size_t e = ((size_t)b * Cc + co0 + co) * Nn + n0 + mp;
            *(uint32_t*)(g_Vth + e) = h;
            *(uint32_t*)(g_Vtl + e) = lo;
        }
    }
}

// ---------------------------------------------------------------------------
// HMMA flash attention, P-in-registers (no P smem round-trip).
// 256 threads; warp = 16 rows x 64-key half (wn). Each warp accumulates
// O[16 rows x 256 ch] for its key half; halves merged in epilogue.
// pitches (b16): Q 264, K/V chunk 72 / 136.
// ---------------------------------------------------------------------------
#define SM_RS  0
#define SM_QH  256
#define SM_QL  (SM_QH + 33792)            // 34048
#define SM_B0H (SM_QL + 33792)            // 67840
#define SM_B0L (SM_B0H + 18432)           // 86272
#define SM_B1H (SM_B0L + 18432)           // 104704
#define SM_B1L (SM_B1H + 18432)           // 123136
#define ATTN_SMEM (SM_B1L + 18432)        // 141568

__global__ __launch_bounds__(256, 1) void attn_kernel(float* __restrict__ out)
{
    extern __shared__ char smem[];
    float* rs = (float*)(smem + SM_RS);
    const uint32_t sbase = smem_u32(smem);

    const int tid  = threadIdx.x;
    const int wid  = tid >> 5;
    const int lane = tid & 31;
    const int b    = blockIdx.y;
    const int m0   = blockIdx.x * BM;

    const int wm = (wid & 3) * 16;    // warp row block
    const int wn = wid >> 2;          // key half

    const int arow   = wm + (lane & 7) + ((lane >> 3) & 1) * 8;
    const int ak     = (lane >> 4) * 8;
    const int bn_row = (lane & 7) + (lane >> 4) * 8;
    const int bk_add = ((lane >> 3) & 1) * 8;

    const uint32_t qbH = sbase + SM_QH, qbL = sbase + SM_QL;

    if (tid < 64) rs[tid] = 0.f;

    {
        const uint4* Gh = (const uint4*)g_Qh;
        const uint4* Gl = (const uint4*)g_Ql;
        uint4* Dh = (uint4*)(smem + SM_QH);
        uint4* Dl = (uint4*)(smem + SM_QL);
#pragma unroll
        for (int l = tid; l < 2048; l += 256) {
            int m = l >> 5, c8 = l & 31;
            size_t gi = (((size_t)b * Nn + m0 + m) * Cc + c8 * 8) >> 3;
            int d = m * 33 + c8;
            Dh[d] = Gh[gi];
            Dl[d] = Gl[gi];
        }
    }

    auto issue_chunk = [&](int ci) {
        int kt2 = ci >> 3, j2 = ci & 7, n02 = kt2 * BN;
        uint32_t bH = sbase + ((ci & 1) ? SM_B1H : SM_B0H);
        uint32_t bL = sbase + ((ci & 1) ? SM_B1L : SM_B0L);
        if (j2 < 4) {
            const char* Gh = (const char*)g_Kh;
            const char* Gl = (const char*)g_Kl;
#pragma unroll
            for (int t = 0; t < 4; ++t) {
                int l = tid + t * 256;
                int n = l >> 3, c8 = l & 7;
                size_t gb = (((size_t)b * Nn + n02 + n) * Cc + j2 * 64 + c8 * 8) * 2;
                uint32_t so = (uint32_t)((n * 72 + c8 * 8) * 2);
                cp16(bH + so, Gh + gb);
                cp16(bL + so, Gl + gb);
            }
        } else {
            int vc = j2 - 4;
            const char* Gh = (const char*)g_Vth;
            const char* Gl = (const char*)g_Vtl;
#pragma unroll
            for (int t = 0; t < 4; ++t) {
                int l = tid + t * 256;
                int c = l >> 4, j8 = l & 15;
                size_t gb = (((size_t)b * Cc + vc * 64 + c) * Nn + n02 + j8 * 8) * 2;
                uint32_t so = (uint32_t)((c * 136 + j8 * 8) * 2);
                cp16(bH + so, Gh + gb);
                cp16(bL + so, Gl + gb);
            }
        }
    };

    // O: 16 rows x 256 ch per warp -> 32 accumulator quads
    float oacc[32][4];
#pragma unroll
    for (int f = 0; f < 32; f++)
#pragma unroll
        for (int e = 0; e < 4; e++) oacc[f][e] = 0.f;

    float sacc[8][4];
    uint32_t pH01[8], pH23[8], pL01[8], pL23[8];   // packed P fragments
    float s0 = 0.f, s1 = 0.f;

    issue_chunk(0);
    CP_COMMIT();

    for (int kt = 0; kt < KT; ++kt) {
        for (int j = 0; j < 8; ++j) {
            const int i = kt * 8 + j;
            CP_WAIT0();
            __syncthreads();
            if (i + 1 < KT * 8) issue_chunk(i + 1);
            CP_COMMIT();

            const uint32_t bH = sbase + ((i & 1) ? SM_B1H : SM_B0H);
            const uint32_t bL = sbase + ((i & 1) ? SM_B1L : SM_B0L);

            if (j < 4) {
                // ------------- S += Q K^T (channel chunk j) -------------
                const int cc = j;
                if (j == 0) {
#pragma unroll
                    for (int f = 0; f < 8; f++)
#pragma unroll
                        for (int e = 0; e < 4; e++) sacc[f][e] = 0.f;
                }
#pragma unroll
                for (int ks = 0; ks < 4; ++ks) {
                    const int k0 = ks * 16;
                    uint32_t qh[4], ql[4];
                    uint32_t qa = (uint32_t)((arow * 264 + cc * 64 + k0 + ak) * 2);
                    LDSM4(qh, qbH + qa);
                    LDSM4(ql, qbL + qa);
                    uint32_t BH[4][4], BL[4][4];
#pragma unroll
                    for (int nb = 0; nb < 4; ++nb) {
                        uint32_t kaddr = (uint32_t)(((wn * 64 + nb * 16 + bn_row) * 72 + k0 + bk_add) * 2);
                        LDSM4(BH[nb], bH + kaddr);
                        LDSM4(BL[nb], bL + kaddr);
                    }
#pragma unroll
                    for (int nb = 0; nb < 4; ++nb) {
                        mma_bf16(sacc[2 * nb],     qh, BH[nb][0], BH[nb][1]);
                        mma_bf16(sacc[2 * nb + 1], qh, BH[nb][2], BH[nb][3]);
                    }
#pragma unroll
                    for (int nb = 0; nb < 4; ++nb) {
                        mma_bf16(sacc[2 * nb],     ql, BH[nb][0], BH[nb][1]);
                        mma_bf16(sacc[2 * nb + 1], ql, BH[nb][2], BH[nb][3]);
                    }
#pragma unroll
                    for (int nb = 0; nb < 4; ++nb) {
                        mma_bf16(sacc[2 * nb],     qh, BL[nb][0], BL[nb][1]);
                        mma_bf16(sacc[2 * nb + 1], qh, BL[nb][2], BL[nb][3]);
                    }
                }
                if (j == 3) {
                    // ---- softmax + pack P fragments in registers ----
#pragma unroll
                    for (int f = 0; f < 8; ++f) {
                        float p0 = __expf(sacc[f][0] - SHIFT);
                        float p1 = __expf(sacc[f][1] - SHIFT);
                        float p2 = __expf(sacc[f][2] - SHIFT);
                        float p3 = __expf(sacc[f][3] - SHIFT);
                        s0 += p0 + p1;
                        s1 += p2 + p3;
                        split_pack(p0, p1, pH01[f], pL01[f]);
                        split_pack(p2, p3, pH23[f], pL23[f]);
                    }
                }
            } else {
                // ------------- O += P V (channel chunk j-4) -------------
                // warp keys: wn*64 .. +63 (local cols of V chunk)
                const int vc = j - 4;
#pragma unroll
                for (int ks = 0; ks < 4; ++ks) {
                    const int k0 = wn * 64 + ks * 16;
                    uint32_t pah[4] = {pH01[2 * ks], pH23[2 * ks],
                                       pH01[2 * ks + 1], pH23[2 * ks + 1]};
                    uint32_t pal[4] = {pL01[2 * ks], pL23[2 * ks],
                                       pL01[2 * ks + 1], pL23[2 * ks + 1]};
#pragma unroll
                    for (int g = 0; g < 2; ++g) {
                        uint32_t VH0[4], VL0[4], VH1[4], VL1[4];
                        uint32_t va0 = (uint32_t)((((2 * g) * 16 + bn_row) * 136 + k0 + bk_add) * 2);
                        uint32_t va1 = (uint32_t)((((2 * g + 1) * 16 + bn_row) * 136 + k0 + bk_add) * 2);
                        LDSM4(VH0, bH + va0);
                        LDSM4(VL0, bL + va0);
                        LDSM4(VH1, bH + va1);
                        LDSM4(VL1, bL + va1);
                        float* o0 = oacc[vc * 8 + g * 4];
                        float* o1 = oacc[vc * 8 + g * 4 + 1];
                        float* o2 = oacc[vc * 8 + g * 4 + 2];
                        float* o3 = oacc[vc * 8 + g * 4 + 3];
                        mma_bf16(o0, pah, VH0[0], VH0[1]);
                        mma_bf16(o1, pah, VH0[2], VH0[3]);
                        mma_bf16(o2, pah, VH1[0], VH1[1]);
                        mma_bf16(o3, pah, VH1[2], VH1[3]);
                        mma_bf16(o0, pal, VH0[0], VH0[1]);
                        mma_bf16(o1, pal, VH0[2], VH0[3]);
                        mma_bf16(o2, pal, VH1[0], VH1[1]);
                        mma_bf16(o3, pal, VH1[2], VH1[3]);
                        mma_bf16(o0, pah, VL0[0], VL0[1]);
                        mma_bf16(o1, pah, VL0[2], VL0[3]);
                        mma_bf16(o2, pah, VL1[0], VL1[1]);
                        mma_bf16(o3, pah, VL1[2], VL1[3]);
                    }
                }
            }
        }
    }

    // ================ epilogue: merge wn halves, scale, store ============
    __syncthreads();
    atomicAdd(&rs[wm + (lane >> 2)], s0);
    atomicAdd(&rs[wm + (lane >> 2) + 8], s1);
    __syncthreads();
    if (tid < 64) rs[tid] = 1.f / rs[tid];
    __syncthreads();

    const int r = wm + (lane >> 2);
    float* st1 = (float*)(smem + SM_QH);     // [64 rows][pitch 260]
    if (wn == 1) {
#pragma unroll
        for (int q = 0; q < 32; ++q) {
            int ch = q * 8 + (lane & 3) * 2;
            st1[r * 260 + ch]           = oacc[q][0];
            st1[r * 260 + ch + 1]       = oacc[q][1];
            st1[(r + 8) * 260 + ch]     = oacc[q][2];
            st1[(r + 8) * 260 + ch + 1] = oacc[q][3];
        }
    }
    __syncthreads();
    float* st2 = (float*)(smem + SM_B0H);    // [256 ch][pitch 68]
    if (wn == 0) {
#pragma unroll
        for (int q = 0; q < 32; ++q) {
            int ch = q * 8 + (lane & 3) * 2;
            st2[ch * 68 + r]           = oacc[q][0] + st1[r * 260 + ch];
            st2[(ch + 1) * 68 + r]     = oacc[q][1] + st1[r * 260 + ch + 1];
            st2[ch * 68 + r + 8]       = oacc[q][2] + st1[(r + 8) * 260 + ch];
            st2[(ch + 1) * 68 + r + 8] = oacc[q][3] + st1[(r + 8) * 260 + ch + 1];
        }
    }
    __syncthreads();
    float* outb = out + (size_t)b * Cc * Nn;
#pragma unroll
    for (int l = tid; l < 16384; l += 256) {
        int ch = l >> 6, m = l & 63;
        outb[(size_t)ch * Nn + m0 + m] = st2[ch * 68 + m] * rs[m];
    }
}

// ---------------------------------------------------------------------------
extern "C" void kernel_launch(void* const* d_in, const int* in_sizes, int n_in,
                              void* d_out, int out_size)
{
    (void)in_sizes; (void)n_in; (void)out_size;
    const float* x  = (const float*)d_in[0];
    const float* y  = (const float*)d_in[1];
    const float* Wq = (const float*)d_in[2];
    const float* bq = (const float*)d_in[3];
    const float* Wk = (const float*)d_in[4];
    const float* bk = (const float*)d_in[5];
    const float* Wv = (const float*)d_in[6];
    const float* bv = (const float*)d_in[7];
    float* out = (float*)d_out;

    prep_xy<<<dim3(2304, 1, 2), 256>>>((const float4*)x, (const float4*)y);
    prep_w<<<dim3(64, 1, 3), 256>>>((const float4*)Wq, (const float4*)Wk,
                                    (const float4*)Wv);
    proj_hmma<<<dim3(Nn / 64, Cc / 64, 24), 128>>>(bq, bk, bv);

    cudaFuncSetAttribute(attn_kernel,
                         cudaFuncAttributeMaxDynamicSharedMemorySize, ATTN_SMEM);
    dim3 ag(Nn / BM, Bb);
    attn_kernel<<<ag, 256, ATTN_SMEM>>>(out);
}

// round 11
// speedup vs baseline: 1.0262x; 1.0054x over previous
#include <cuda_runtime.h>
#include <cuda_bf16.h>
#include <cuda_fp16.h>
#include <math.h>
#include <stdint.h>

#define Bb 8
#define Cc 256
#define Nn 2304
#define BM 64
#define BN 128
#define KT (Nn / BN)      // 18

// ---------------- global scratch ----------------
__device__ __align__(16) unsigned short g_Qh[(size_t)Bb * Nn * Cc];   // bf16 hi
__device__ __align__(16) unsigned short g_Ql[(size_t)Bb * Nn * Cc];   // bf16 lo
__device__ __align__(16) unsigned short g_Kh[(size_t)Bb * Nn * Cc];   // bf16 hi
__device__ __align__(16) unsigned short g_Kl[(size_t)Bb * Nn * Cc];   // bf16 lo
__device__ __align__(16) unsigned short g_Vt[(size_t)Bb * Cc * Nn];   // fp16 single, channel-major
// inputs split to bf16 hi/lo (channel-major, same layout as x/y)
__device__ __align__(16) unsigned short g_Xh[(size_t)Bb * Cc * Nn];
__device__ __align__(16) unsigned short g_Xl[(size_t)Bb * Cc * Nn];
__device__ __align__(16) unsigned short g_Yh[(size_t)Bb * Cc * Nn];
__device__ __align__(16) unsigned short g_Yl[(size_t)Bb * Cc * Nn];
// weights split ([co][ci], row-major)
__device__ __align__(16) unsigned short g_Wh[3][Cc * Cc];
__device__ __align__(16) unsigned short g_Wl[3][Cc * Cc];

// ---------------- helpers ----------------
__device__ __forceinline__ uint32_t smem_u32(const void* p) {
    uint32_t a;
    asm("{ .reg .u64 t; cvta.to.shared.u64 t, %1; cvt.u32.u64 %0, t; }" : "=r"(a) : "l"(p));
    return a;
}

#define LDSM4(r, addr) \
    asm volatile("ldmatrix.sync.aligned.m8n8.x4.shared.b16 {%0,%1,%2,%3}, [%4];" \
        : "=r"((r)[0]), "=r"((r)[1]), "=r"((r)[2]), "=r"((r)[3]) : "r"(addr))
#define LDSM4T(r, addr) \
    asm volatile("ldmatrix.sync.aligned.m8n8.x4.trans.shared.b16 {%0,%1,%2,%3}, [%4];" \
        : "=r"((r)[0]), "=r"((r)[1]), "=r"((r)[2]), "=r"((r)[3]) : "r"(addr))

__device__ __forceinline__ void mma_bf16(float* c, const uint32_t* a,
                                         uint32_t b0, uint32_t b1) {
    asm volatile(
        "mma.sync.aligned.m16n8k16.row.col.f32.bf16.bf16.f32 "
        "{%0,%1,%2,%3}, {%4,%5,%6,%7}, {%8,%9}, {%0,%1,%2,%3};"
        : "+f"(c[0]), "+f"(c[1]), "+f"(c[2]), "+f"(c[3])
        : "r"(a[0]), "r"(a[1]), "r"(a[2]), "r"(a[3]), "r"(b0), "r"(b1));
}

__device__ __forceinline__ void mma_fp16(float* c, const uint32_t* a,
                                         uint32_t b0, uint32_t b1) {
    asm volatile(
        "mma.sync.aligned.m16n8k16.row.col.f32.f16.f16.f32 "
        "{%0,%1,%2,%3}, {%4,%5,%6,%7}, {%8,%9}, {%0,%1,%2,%3};"
        : "+f"(c[0]), "+f"(c[1]), "+f"(c[2]), "+f"(c[3])
        : "r"(a[0]), "r"(a[1]), "r"(a[2]), "r"(a[3]), "r"(b0), "r"(b1));
}

__device__ __forceinline__ void cp16(uint32_t s, const void* g) {
    asm volatile("cp.async.cg.shared.global [%0], [%1], 16;" :: "r"(s), "l"(g) : "memory");
}
#define CP_COMMIT() asm volatile("cp.async.commit_group;" ::: "memory")
#define CP_WAIT0()  asm volatile("cp.async.wait_group 0;" ::: "memory")

__device__ __forceinline__ void split2(float v, unsigned short& h, unsigned short& l) {
    __nv_bfloat16 bh = __float2bfloat16(v);
    float r = v - __bfloat162float(bh);
    h = __bfloat16_as_ushort(bh);
    l = __bfloat16_as_ushort(__float2bfloat16(r));
}

__device__ __forceinline__ void split_pack(float a, float b, uint32_t& h, uint32_t& l) {
    unsigned short ah, al, bh, bl;
    split2(a, ah, al);
    split2(b, bh, bl);
    h = (uint32_t)ah | ((uint32_t)bh << 16);
    l = (uint32_t)al | ((uint32_t)bl << 16);
}

__device__ __forceinline__ uint32_t pack_h2(float a, float b) {
    __half2 h = __floats2half2_rn(a, b);
    return *(uint32_t*)&h;
}

// ---------------------------------------------------------------------------
// Prep: split x,y (fp32) -> bf16 hi/lo, same layout. grid (2304,1,2) x 256
// ---------------------------------------------------------------------------
__global__ __launch_bounds__(256) void prep_xy(const float4* __restrict__ x,
                                               const float4* __restrict__ y)
{
    const int z = blockIdx.z;
    const float4* src = z ? y : x;
    uint4* H = (uint4*)(z ? g_Yh : g_Xh);
    uint4* L = (uint4*)(z ? g_Yl : g_Xl);
    size_t i = (size_t)blockIdx.x * 512 + threadIdx.x * 2;
    float4 f0 = src[i], f1 = src[i + 1];
    uint4 h, l;
    split_pack(f0.x, f0.y, h.x, l.x);
    split_pack(f0.z, f0.w, h.y, l.y);
    split_pack(f1.x, f1.y, h.z, l.z);
    split_pack(f1.z, f1.w, h.w, l.w);
    H[i >> 1] = h;
    L[i >> 1] = l;
}

// Prep: split Wq/Wk/Wv. grid (64,1,3) x 256
__global__ __launch_bounds__(256) void prep_w(const float4* __restrict__ Wq,
                                              const float4* __restrict__ Wk,
                                              const float4* __restrict__ Wv)
{
    const int z = blockIdx.z;
    const float4* src = (z == 0) ? Wq : ((z == 1) ? Wk : Wv);
    uint2* H = (uint2*)g_Wh[z];
    uint2* L = (uint2*)g_Wl[z];
    int i = blockIdx.x * 256 + threadIdx.x;
    float4 f = src[i];
    uint2 h, l;
    split_pack(f.x, f.y, h.x, l.x);
    split_pack(f.z, f.w, h.y, l.y);
    H[i] = h;
    L[i] = l;
}

// ---------------------------------------------------------------------------
// HMMA projections (bf16x3): 64tok x 64co per CTA, 128 threads (4 warps).
// ---------------------------------------------------------------------------
#define PX_H 0
#define PX_L 9216
#define PW_H 18432
#define PW_L 27648

__global__ __launch_bounds__(128) void proj_hmma(
    const float* __restrict__ bq, const float* __restrict__ bk,
    const float* __restrict__ bv)
{
    __shared__ char psm[36864];
    const uint32_t sb = smem_u32(psm);

    const int tid  = threadIdx.x;
    const int wid  = tid >> 5;
    const int lane = tid & 31;
    const int n0    = blockIdx.x * 64;
    const int co0   = blockIdx.y * 64;
    const int which = blockIdx.z >> 3;
    const int b     = blockIdx.z & 7;

    const unsigned short* Xh = (which == 0) ? g_Xh : g_Yh;
    const unsigned short* Xl = (which == 0) ? g_Xl : g_Yl;
    const unsigned short* Wh = g_Wh[which];
    const unsigned short* Wl = g_Wl[which];
    const float* bias = (which == 0) ? bq : ((which == 1) ? bk : bv);

    const int a_ci = (lane & 7) + ((lane >> 4) & 1) * 8;
    const int a_m  = wid * 16 + ((lane >> 3) & 1) * 8;
    const int b_row = (lane & 7) + (lane >> 4) * 8;
    const int b_k   = ((lane >> 3) & 1) * 8;

    float acc[8][4];
#pragma unroll
    for (int j = 0; j < 8; j++)
#pragma unroll
        for (int e = 0; e < 4; e++) acc[j][e] = 0.f;

    for (int ck = 0; ck < 4; ++ck) {
#pragma unroll
        for (int t = 0; t < 4; ++t) {
            int l = tid + t * 128;
            int r = l >> 3, s = l & 7;
            size_t xg = (((size_t)b * Cc + ck * 64 + r) * Nn + n0 + s * 8) * 2;
            uint32_t xo = (uint32_t)(r * 144 + s * 16);
            cp16(sb + PX_H + xo, (const char*)Xh + xg);
            cp16(sb + PX_L + xo, (const char*)Xl + xg);
            size_t wg = (size_t)((co0 + r) * Cc + ck * 64 + s * 8) * 2;
            cp16(sb + PW_H + xo, (const char*)Wh + wg);
            cp16(sb + PW_L + xo, (const char*)Wl + wg);
        }
        CP_COMMIT();
        CP_WAIT0();
        __syncthreads();

#pragma unroll
        for (int ks = 0; ks < 4; ++ks) {
            uint32_t ah[4], al4[4];
            uint32_t aa = (uint32_t)((ks * 16 + a_ci) * 144 + a_m * 2);
            LDSM4T(ah, sb + PX_H + aa);
            LDSM4T(al4, sb + PX_L + aa);
            uint32_t BH[4][4], BL[4][4];
#pragma unroll
            for (int nb = 0; nb < 4; ++nb) {
                uint32_t ba = (uint32_t)((nb * 16 + b_row) * 144 + (ks * 16 + b_k) * 2);
                LDSM4(BH[nb], sb + PW_H + ba);
                LDSM4(BL[nb], sb + PW_L + ba);
            }
#pragma unroll
            for (int nb = 0; nb < 4; ++nb) {
                mma_bf16(acc[2 * nb],     ah, BH[nb][0], BH[nb][1]);
                mma_bf16(acc[2 * nb + 1], ah, BH[nb][2], BH[nb][3]);
            }
#pragma unroll
            for (int nb = 0; nb < 4; ++nb) {
                mma_bf16(acc[2 * nb],     al4, BH[nb][0], BH[nb][1]);
                mma_bf16(acc[2 * nb + 1], al4, BH[nb][2], BH[nb][3]);
            }
#pragma unroll
            for (int nb = 0; nb < 4; ++nb) {
                mma_bf16(acc[2 * nb],     ah, BL[nb][0], BL[nb][1]);
                mma_bf16(acc[2 * nb + 1], ah, BL[nb][2], BL[nb][3]);
            }
        }
        __syncthreads();
    }

    const int m1 = wid * 16 + (lane >> 2);

    if (which < 2) {
        unsigned short* Gh = which ? g_Kh : g_Qh;
        unsigned short* Gl = which ? g_Kl : g_Ql;
#pragma unroll
        for (int j = 0; j < 8; ++j) {
            int co = j * 8 + (lane & 3) * 2;
            float b0 = bias[co0 + co], b1 = bias[co0 + co + 1];
            uint32_t h01, l01, h23, l23;
            split_pack(acc[j][0] + b0, acc[j][1] + b1, h01, l01);
            split_pack(acc[j][2] + b0, acc[j][3] + b1, h23, l23);
            size_t e1 = ((size_t)b * Nn + n0 + m1) * Cc + co0 + co;
            size_t e2 = e1 + 8 * (size_t)Cc;
            *(uint32_t*)(Gh + e1) = h01;
            *(uint32_t*)(Gl + e1) = l01;
            *(uint32_t*)(Gh + e2) = h23;
            *(uint32_t*)(Gl + e2) = l23;
        }
    } else {
        float* stage = (float*)psm;     // [co 64][m 68]
#pragma unroll
        for (int j = 0; j < 8; ++j) {
            int co = j * 8 + (lane & 3) * 2;
            float b0 = bias[co0 + co], b1 = bias[co0 + co + 1];
            stage[co * 68 + m1]           = acc[j][0] + b0;
            stage[(co + 1) * 68 + m1]     = acc[j][1] + b1;
            stage[co * 68 + m1 + 8]       = acc[j][2] + b0;
            stage[(co + 1) * 68 + m1 + 8] = acc[j][3] + b1;
        }
        __syncthreads();
#pragma unroll
        for (int l = tid; l < 2048; l += 128) {
            int co = l >> 5, mp = (l & 31) * 2;
            float v0 = stage[co * 68 + mp], v1 = stage[co * 68 + mp + 1];
            size_t e = ((size_t)b * Cc + co0 + co) * Nn + n0 + mp;
            *(uint32_t*)(g_Vt + e) = pack_h2(v0, v1);   // fp16 single
        }
    }
}

// ---------------------------------------------------------------------------
// HMMA flash attention: bf16x3 S-phase, fp16x1 PV, per-warp-half online max.
// 256 threads; warp = 16 rows x 64-key half (wn). Each half accumulates
// O[16 rows x 256 ch] with its own running max; merged in epilogue.
// ---------------------------------------------------------------------------
#define SM_QH  256
#define SM_QL  (SM_QH + 33792)            // 34048
#define SM_B0H (SM_QL + 33792)            // 67840
#define SM_B0L (SM_B0H + 18432)           // 86272
#define SM_B1H (SM_B0L + 18432)           // 104704
#define SM_B1L (SM_B1H + 18432)           // 123136
#define SM_STATS 137472                    // 384 floats (epilogue only)
#define ATTN_SMEM (SM_B1L + 18432)        // 141568

__global__ __launch_bounds__(256, 1) void attn_kernel(float* __restrict__ out)
{
    extern __shared__ char smem[];
    const uint32_t sbase = smem_u32(smem);

    const int tid  = threadIdx.x;
    const int wid  = tid >> 5;
    const int lane = tid & 31;
    const int b    = blockIdx.y;
    const int m0   = blockIdx.x * BM;

    const int wm = (wid & 3) * 16;    // warp row block
    const int wn = wid >> 2;          // key half

    const int arow   = wm + (lane & 7) + ((lane >> 3) & 1) * 8;
    const int ak     = (lane >> 4) * 8;
    const int bn_row = (lane & 7) + (lane >> 4) * 8;
    const int bk_add = ((lane >> 3) & 1) * 8;

    const uint32_t qbH = sbase + SM_QH, qbL = sbase + SM_QL;

    {
        const uint4* Gh = (const uint4*)g_Qh;
        const uint4* Gl = (const uint4*)g_Ql;
        uint4* Dh = (uint4*)(smem + SM_QH);
        uint4* Dl = (uint4*)(smem + SM_QL);
#pragma unroll
        for (int l = tid; l < 2048; l += 256) {
            int m = l >> 5, c8 = l & 31;
            size_t gi = (((size_t)b * Nn + m0 + m) * Cc + c8 * 8) >> 3;
            int d = m * 33 + c8;
            Dh[d] = Gh[gi];
            Dl[d] = Gl[gi];
        }
    }

    auto issue_chunk = [&](int ci) {
        int kt2 = ci >> 3, j2 = ci & 7, n02 = kt2 * BN;
        uint32_t bH = sbase + ((ci & 1) ? SM_B1H : SM_B0H);
        uint32_t bL = sbase + ((ci & 1) ? SM_B1L : SM_B0L);
        if (j2 < 4) {
            const char* Gh = (const char*)g_Kh;
            const char* Gl = (const char*)g_Kl;
#pragma unroll
            for (int t = 0; t < 4; ++t) {
                int l = tid + t * 256;
                int n = l >> 3, c8 = l & 7;
                size_t gb = (((size_t)b * Nn + n02 + n) * Cc + j2 * 64 + c8 * 8) * 2;
                uint32_t so = (uint32_t)((n * 72 + c8 * 8) * 2);
                cp16(bH + so, Gh + gb);
                cp16(bL + so, Gl + gb);
            }
        } else {
            int vc = j2 - 4;
            const char* Gv = (const char*)g_Vt;
#pragma unroll
            for (int t = 0; t < 4; ++t) {
                int l = tid + t * 256;
                int c = l >> 4, j8 = l & 15;
                size_t gb = (((size_t)b * Cc + vc * 64 + c) * Nn + n02 + j8 * 8) * 2;
                uint32_t so = (uint32_t)((c * 136 + j8 * 8) * 2);
                cp16(bH + so, Gv + gb);
            }
        }
    };

    // O: 16 rows x 256 ch per warp half -> 32 accumulator quads
    float oacc[32][4];
#pragma unroll
    for (int f = 0; f < 32; f++)
#pragma unroll
        for (int e = 0; e < 4; e++) oacc[f][e] = 0.f;

    float sacc[8][4];
    uint32_t pF01[8], pF23[8];           // fp16x2 P fragments
    float s0 = 0.f, s1 = 0.f;
    float m_a = -1e30f, m_b = -1e30f;    // running row maxes (rows r, r+8)

    issue_chunk(0);
    CP_COMMIT();

    for (int kt = 0; kt < KT; ++kt) {
        for (int j = 0; j < 8; ++j) {
            const int i = kt * 8 + j;
            CP_WAIT0();
            __syncthreads();
            if (i + 1 < KT * 8) issue_chunk(i + 1);
            CP_COMMIT();

            const uint32_t bH = sbase + ((i & 1) ? SM_B1H : SM_B0H);
            const uint32_t bL = sbase + ((i & 1) ? SM_B1L : SM_B0L);

            if (j < 4) {
                // ------------- S += Q K^T (channel chunk j), bf16x3 -------------
                const int cc = j;
                if (j == 0) {
#pragma unroll
                    for (int f = 0; f < 8; f++)
#pragma unroll
                        for (int e = 0; e < 4; e++) sacc[f][e] = 0.f;
                }
#pragma unroll
                for (int ks = 0; ks < 4; ++ks) {
                    const int k0 = ks * 16;
                    uint32_t qh[4], ql[4];
                    uint32_t qa = (uint32_t)((arow * 264 + cc * 64 + k0 + ak) * 2);
                    LDSM4(qh, qbH + qa);
                    LDSM4(ql, qbL + qa);
                    uint32_t BH[4][4], BL[4][4];
#pragma unroll
                    for (int nb = 0; nb < 4; ++nb) {
                        uint32_t kaddr = (uint32_t)(((wn * 64 + nb * 16 + bn_row) * 72 + k0 + bk_add) * 2);
                        LDSM4(BH[nb], bH + kaddr);
                        LDSM4(BL[nb], bL + kaddr);
                    }
#pragma unroll
                    for (int nb = 0; nb < 4; ++nb) {
                        mma_bf16(sacc[2 * nb],     qh, BH[nb][0], BH[nb][1]);
                        mma_bf16(sacc[2 * nb + 1], qh, BH[nb][2], BH[nb][3]);
                    }
#pragma unroll
                    for (int nb = 0; nb < 4; ++nb) {
                        mma_bf16(sacc[2 * nb],     ql, BH[nb][0], BH[nb][1]);
                        mma_bf16(sacc[2 * nb + 1], ql, BH[nb][2], BH[nb][3]);
                    }
#pragma unroll
                    for (int nb = 0; nb < 4; ++nb) {
                        mma_bf16(sacc[2 * nb],     qh, BL[nb][0], BL[nb][1]);
                        mma_bf16(sacc[2 * nb + 1], qh, BL[nb][2], BL[nb][3]);
                    }
                }
                if (j == 3) {
                    // ---- online softmax (per warp half), fp16 P pack ----
                    float ma = -1e30f, mb = -1e30f;
#pragma unroll
                    for (int f = 0; f < 8; ++f) {
                        ma = fmaxf(ma, fmaxf(sacc[f][0], sacc[f][1]));
                        mb = fmaxf(mb, fmaxf(sacc[f][2], sacc[f][3]));
                    }
                    ma = fmaxf(ma, __shfl_xor_sync(0xffffffffu, ma, 1));
                    ma = fmaxf(ma, __shfl_xor_sync(0xffffffffu, ma, 2));
                    mb = fmaxf(mb, __shfl_xor_sync(0xffffffffu, mb, 1));
                    mb = fmaxf(mb, __shfl_xor_sync(0xffffffffu, mb, 2));
                    float mna = fmaxf(m_a, ma), mnb = fmaxf(m_b, mb);
                    float aa = __expf(m_a - mna), ab = __expf(m_b - mnb);
                    m_a = mna; m_b = mnb;
                    s0 *= aa; s1 *= ab;
#pragma unroll
                    for (int f = 0; f < 8; ++f) {
                        float p0 = __expf(sacc[f][0] - m_a);
                        float p1 = __expf(sacc[f][1] - m_a);
                        float p2 = __expf(sacc[f][2] - m_b);
                        float p3 = __expf(sacc[f][3] - m_b);
                        s0 += p0 + p1;
                        s1 += p2 + p3;
                        pF01[f] = pack_h2(p0, p1);
                        pF23[f] = pack_h2(p2, p3);
                    }
#pragma unroll
                    for (int f = 0; f < 32; ++f) {
                        oacc[f][0] *= aa; oacc[f][1] *= aa;
                        oacc[f][2] *= ab; oacc[f][3] *= ab;
                    }
                }
            } else {
                // ------------- O += P V (channel chunk j-4), fp16x1 -------------
                const int vc = j - 4;
#pragma unroll
                for (int ks = 0; ks < 4; ++ks) {
                    const int k0 = wn * 64 + ks * 16;
                    uint32_t paf[4] = {pF01[2 * ks], pF23[2 * ks],
                                       pF01[2 * ks + 1], pF23[2 * ks + 1]};
#pragma unroll
                    for (int g = 0; g < 2; ++g) {
                        uint32_t VH0[4], VH1[4];
                        uint32_t va0 = (uint32_t)((((2 * g) * 16 + bn_row) * 136 + k0 + bk_add) * 2);
                        uint32_t va1 = (uint32_t)((((2 * g + 1) * 16 + bn_row) * 136 + k0 + bk_add) * 2);
                        LDSM4(VH0, bH + va0);
                        LDSM4(VH1, bH + va1);
                        mma_fp16(oacc[vc * 8 + g * 4],     paf, VH0[0], VH0[1]);
                        mma_fp16(oacc[vc * 8 + g * 4 + 1], paf, VH0[2], VH0[3]);
                        mma_fp16(oacc[vc * 8 + g * 4 + 2], paf, VH1[0], VH1[1]);
                        mma_fp16(oacc[vc * 8 + g * 4 + 3], paf, VH1[2], VH1[3]);
                    }
                }
            }
        }
    }

    // ================ epilogue: merge halves with max factors ============
    __syncthreads();
    s0 += __shfl_xor_sync(0xffffffffu, s0, 1);
    s0 += __shfl_xor_sync(0xffffffffu, s0, 2);
    s1 += __shfl_xor_sync(0xffffffffu, s1, 1);
    s1 += __shfl_xor_sync(0xffffffffu, s1, 2);

    float* m_sm  = (float*)(smem + SM_STATS);        // [128]
    float* rs_sm = m_sm + 128;                       // [128]
    float* g0_sm = rs_sm + 128;                      // [64]
    float* g1_sm = g0_sm + 64;                       // [64]
    const int r = wm + (lane >> 2);
    if ((lane & 3) == 0) {
        m_sm[wn * 64 + r]      = m_a;
        rs_sm[wn * 64 + r]     = s0;
        m_sm[wn * 64 + r + 8]  = m_b;
        rs_sm[wn * 64 + r + 8] = s1;
    }
    __syncthreads();
    if (tid < 64) {
        float m0v = m_sm[tid], m1v = m_sm[64 + tid];
        float r0 = rs_sm[tid], r1 = rs_sm[64 + tid];
        float REF = fmaxf(m0v, m1v);
        float f0 = __expf(m0v - REF), f1 = __expf(m1v - REF);
        float inv = 1.f / (f0 * r0 + f1 * r1);
        g0_sm[tid] = f0 * inv;
        g1_sm[tid] = f1 * inv;
    }
    __syncthreads();

    float* st1 = (float*)(smem + SM_QH);     // [64 rows][pitch 260]
    if (wn == 1) {
        float ga = g1_sm[r], gb = g1_sm[r + 8];
#pragma unroll
        for (int q = 0; q < 32; ++q) {
            int ch = q * 8 + (lane & 3) * 2;
            st1[r * 260 + ch]           = oacc[q][0] * ga;
            st1[r * 260 + ch + 1]       = oacc[q][1] * ga;
            st1[(r + 8) * 260 + ch]     = oacc[q][2] * gb;
            st1[(r + 8) * 260 + ch + 1] = oacc[q][3] * gb;
        }
    }
    __syncthreads();
    float* st2 = (float*)(smem + SM_B0H);    // [256 ch][pitch 68]
    if (wn == 0) {
        float ga = g0_sm[r], gb = g0_sm[r + 8];
#pragma unroll
        for (int q = 0; q < 32; ++q) {
            int ch = q * 8 + (lane & 3) * 2;
            st2[ch * 68 + r]           = oacc[q][0] * ga + st1[r * 260 + ch];
            st2[(ch + 1) * 68 + r]     = oacc[q][1] * ga + st1[r * 260 + ch + 1];
            st2[ch * 68 + r + 8]       = oacc[q][2] * gb + st1[(r + 8) * 260 + ch];
            st2[(ch + 1) * 68 + r + 8] = oacc[q][3] * gb + st1[(r + 8) * 260 + ch + 1];
        }
    }
    __syncthreads();
    float* outb = out + (size_t)b * Cc * Nn;
#pragma unroll
    for (int l = tid; l < 16384; l += 256) {
        int ch = l >> 6, m = l & 63;
        outb[(size_t)ch * Nn + m0 + m] = st2[ch * 68 + m];
    }
}

// ---------------------------------------------------------------------------
extern "C" void kernel_launch(void* const* d_in, const int* in_sizes, int n_in,
                              void* d_out, int out_size)
{
    (void)in_sizes; (void)n_in; (void)out_size;
    const float* x  = (const float*)d_in[0];
    const float* y  = (const float*)d_in[1];
    const float* Wq = (const float*)d_in[2];
    const float* bq = (const float*)d_in[3];
    const float* Wk = (const float*)d_in[4];
    const float* bk = (const float*)d_in[5];
    const float* Wv = (const float*)d_in[6];
    const float* bv = (const float*)d_in[7];
    float* out = (float*)d_out;

    prep_xy<<<dim3(2304, 1, 2), 256>>>((const float4*)x, (const float4*)y);
    prep_w<<<dim3(64, 1, 3), 256>>>((const float4*)Wq, (const float4*)Wk,
                                    (const float4*)Wv);
    proj_hmma<<<dim3(Nn / 64, Cc / 64, 24), 128>>>(bq, bk, bv);

    cudaFuncSetAttribute(attn_kernel,
                         cudaFuncAttributeMaxDynamicSharedMemorySize, ATTN_SMEM);
    dim3 ag(Nn / BM, Bb);
    attn_kernel<<<ag, 256, ATTN_SMEM>>>(out);
}

// round 12
// speedup vs baseline: 1.1457x; 1.1165x over previous
#include <cuda_runtime.h>
#include <cuda_bf16.h>
#include <cuda_fp16.h>
#include <math.h>
#include <stdint.h>

#define Bb 8
#define Cc 256
#define Nn 2304
#define BM 64
#define TN 64             // keys per tile
#define NT (Nn / TN)      // 36 tiles, split even/odd between groups

// ---------------- global scratch ----------------
__device__ __align__(16) unsigned short g_Qh[(size_t)Bb * Nn * Cc];   // bf16 hi
__device__ __align__(16) unsigned short g_Ql[(size_t)Bb * Nn * Cc];   // bf16 lo
__device__ __align__(16) unsigned short g_Kh[(size_t)Bb * Nn * Cc];   // bf16 hi
__device__ __align__(16) unsigned short g_Kl[(size_t)Bb * Nn * Cc];   // bf16 lo
__device__ __align__(16) unsigned short g_Vt[(size_t)Bb * Cc * Nn];   // fp16, channel-major
// inputs split to bf16 hi/lo (channel-major, same layout as x/y)
__device__ __align__(16) unsigned short g_Xh[(size_t)Bb * Cc * Nn];
__device__ __align__(16) unsigned short g_Xl[(size_t)Bb * Cc * Nn];
__device__ __align__(16) unsigned short g_Yh[(size_t)Bb * Cc * Nn];
__device__ __align__(16) unsigned short g_Yl[(size_t)Bb * Cc * Nn];
// weights split ([co][ci], row-major)
__device__ __align__(16) unsigned short g_Wh[3][Cc * Cc];
__device__ __align__(16) unsigned short g_Wl[3][Cc * Cc];

// ---------------- helpers ----------------
__device__ __forceinline__ uint32_t smem_u32(const void* p) {
    uint32_t a;
    asm("{ .reg .u64 t; cvta.to.shared.u64 t, %1; cvt.u32.u64 %0, t; }" : "=r"(a) : "l"(p));
    return a;
}

#define LDSM4(r, addr) \
    asm volatile("ldmatrix.sync.aligned.m8n8.x4.shared.b16 {%0,%1,%2,%3}, [%4];" \
        : "=r"((r)[0]), "=r"((r)[1]), "=r"((r)[2]), "=r"((r)[3]) : "r"(addr))
#define LDSM4T(r, addr) \
    asm volatile("ldmatrix.sync.aligned.m8n8.x4.trans.shared.b16 {%0,%1,%2,%3}, [%4];" \
        : "=r"((r)[0]), "=r"((r)[1]), "=r"((r)[2]), "=r"((r)[3]) : "r"(addr))

#define GBAR(id) asm volatile("bar.sync %0, 128;" :: "r"(id) : "memory")

__device__ __forceinline__ void mma_bf16(float* c, const uint32_t* a,
                                         uint32_t b0, uint32_t b1) {
    asm volatile(
        "mma.sync.aligned.m16n8k16.row.col.f32.bf16.bf16.f32 "
        "{%0,%1,%2,%3}, {%4,%5,%6,%7}, {%8,%9}, {%0,%1,%2,%3};"
        : "+f"(c[0]), "+f"(c[1]), "+f"(c[2]), "+f"(c[3])
        : "r"(a[0]), "r"(a[1]), "r"(a[2]), "r"(a[3]), "r"(b0), "r"(b1));
}

__device__ __forceinline__ void mma_fp16(float* c, const uint32_t* a,
                                         uint32_t b0, uint32_t b1) {
    asm volatile(
        "mma.sync.aligned.m16n8k16.row.col.f32.f16.f16.f32 "
        "{%0,%1,%2,%3}, {%4,%5,%6,%7}, {%8,%9}, {%0,%1,%2,%3};"
        : "+f"(c[0]), "+f"(c[1]), "+f"(c[2]), "+f"(c[3])
        : "r"(a[0]), "r"(a[1]), "r"(a[2]), "r"(a[3]), "r"(b0), "r"(b1));
}

__device__ __forceinline__ void cp16(uint32_t s, const void* g) {
    asm volatile("cp.async.cg.shared.global [%0], [%1], 16;" :: "r"(s), "l"(g) : "memory");
}
#define CP_COMMIT() asm volatile("cp.async.commit_group;" ::: "memory")
#define CP_WAIT0()  asm volatile("cp.async.wait_group 0;" ::: "memory")

__device__ __forceinline__ void split2(float v, unsigned short& h, unsigned short& l) {
    __nv_bfloat16 bh = __float2bfloat16(v);
    float r = v - __bfloat162float(bh);
    h = __bfloat16_as_ushort(bh);
    l = __bfloat16_as_ushort(__float2bfloat16(r));
}

__device__ __forceinline__ void split_pack(float a, float b, uint32_t& h, uint32_t& l) {
    unsigned short ah, al, bh, bl;
    split2(a, ah, al);
    split2(b, bh, bl);
    h = (uint32_t)ah | ((uint32_t)bh << 16);
    l = (uint32_t)al | ((uint32_t)bl << 16);
}

__device__ __forceinline__ uint32_t pack_h2(float a, float b) {
    __half2 h = __floats2half2_rn(a, b);
    return *(uint32_t*)&h;
}

// ---------------------------------------------------------------------------
// Prep: split x,y (fp32) -> bf16 hi/lo. grid (2304,1,2) x 256
// ---------------------------------------------------------------------------
__global__ __launch_bounds__(256) void prep_xy(const float4* __restrict__ x,
                                               const float4* __restrict__ y)
{
    const int z = blockIdx.z;
    const float4* src = z ? y : x;
    uint4* H = (uint4*)(z ? g_Yh : g_Xh);
    uint4* L = (uint4*)(z ? g_Yl : g_Xl);
    size_t i = (size_t)blockIdx.x * 512 + threadIdx.x * 2;
    float4 f0 = src[i], f1 = src[i + 1];
    uint4 h, l;
    split_pack(f0.x, f0.y, h.x, l.x);
    split_pack(f0.z, f0.w, h.y, l.y);
    split_pack(f1.x, f1.y, h.z, l.z);
    split_pack(f1.z, f1.w, h.w, l.w);
    H[i >> 1] = h;
    L[i >> 1] = l;
}

// Prep: split Wq/Wk/Wv. grid (64,1,3) x 256
__global__ __launch_bounds__(256) void prep_w(const float4* __restrict__ Wq,
                                              const float4* __restrict__ Wk,
                                              const float4* __restrict__ Wv)
{
    const int z = blockIdx.z;
    const float4* src = (z == 0) ? Wq : ((z == 1) ? Wk : Wv);
    uint2* H = (uint2*)g_Wh[z];
    uint2* L = (uint2*)g_Wl[z];
    int i = blockIdx.x * 256 + threadIdx.x;
    float4 f = src[i];
    uint2 h, l;
    split_pack(f.x, f.y, h.x, l.x);
    split_pack(f.z, f.w, h.y, l.y);
    H[i] = h;
    L[i] = l;
}

// ---------------------------------------------------------------------------
// HMMA projections (bf16x3): 64tok x 64co per CTA, 128 threads (4 warps).
// ---------------------------------------------------------------------------
#define PX_H 0
#define PX_L 9216
#define PW_H 18432
#define PW_L 27648

__global__ __launch_bounds__(128) void proj_hmma(
    const float* __restrict__ bq, const float* __restrict__ bk,
    const float* __restrict__ bv)
{
    __shared__ char psm[36864];
    const uint32_t sb = smem_u32(psm);

    const int tid  = threadIdx.x;
    const int wid  = tid >> 5;
    const int lane = tid & 31;
    const int n0    = blockIdx.x * 64;
    const int co0   = blockIdx.y * 64;
    const int which = blockIdx.z >> 3;
    const int b     = blockIdx.z & 7;

    const unsigned short* Xh = (which == 0) ? g_Xh : g_Yh;
    const unsigned short* Xl = (which == 0) ? g_Xl : g_Yl;
    const unsigned short* Wh = g_Wh[which];
    const unsigned short* Wl = g_Wl[which];
    const float* bias = (which == 0) ? bq : ((which == 1) ? bk : bv);

    const int a_ci = (lane & 7) + ((lane >> 4) & 1) * 8;
    const int a_m  = wid * 16 + ((lane >> 3) & 1) * 8;
    const int b_row = (lane & 7) + (lane >> 4) * 8;
    const int b_k   = ((lane >> 3) & 1) * 8;

    float acc[8][4];
#pragma unroll
    for (int j = 0; j < 8; j++)
#pragma unroll
        for (int e = 0; e < 4; e++) acc[j][e] = 0.f;

    for (int ck = 0; ck < 4; ++ck) {
#pragma unroll
        for (int t = 0; t < 4; ++t) {
            int l = tid + t * 128;
            int r = l >> 3, s = l & 7;
            size_t xg = (((size_t)b * Cc + ck * 64 + r) * Nn + n0 + s * 8) * 2;
            uint32_t xo = (uint32_t)(r * 144 + s * 16);
            cp16(sb + PX_H + xo, (const char*)Xh + xg);
            cp16(sb + PX_L + xo, (const char*)Xl + xg);
            size_t wg = (size_t)((co0 + r) * Cc + ck * 64 + s * 8) * 2;
            cp16(sb + PW_H + xo, (const char*)Wh + wg);
            cp16(sb + PW_L + xo, (const char*)Wl + wg);
        }
        CP_COMMIT();
        CP_WAIT0();
        __syncthreads();

#pragma unroll
        for (int ks = 0; ks < 4; ++ks) {
            uint32_t ah[4], al4[4];
            uint32_t aa = (uint32_t)((ks * 16 + a_ci) * 144 + a_m * 2);
            LDSM4T(ah, sb + PX_H + aa);
            LDSM4T(al4, sb + PX_L + aa);
            uint32_t BH[4][4], BL[4][4];
#pragma unroll
            for (int nb = 0; nb < 4; ++nb) {
                uint32_t ba = (uint32_t)((nb * 16 + b_row) * 144 + (ks * 16 + b_k) * 2);
                LDSM4(BH[nb], sb + PW_H + ba);
                LDSM4(BL[nb], sb + PW_L + ba);
            }
#pragma unroll
            for (int nb = 0; nb < 4; ++nb) {
                mma_bf16(acc[2 * nb],     ah, BH[nb][0], BH[nb][1]);
                mma_bf16(acc[2 * nb + 1], ah, BH[nb][2], BH[nb][3]);
            }
#pragma unroll
            for (int nb = 0; nb < 4; ++nb) {
                mma_bf16(acc[2 * nb],     al4, BH[nb][0], BH[nb][1]);
                mma_bf16(acc[2 * nb + 1], al4, BH[nb][2], BH[nb][3]);
            }
#pragma unroll
            for (int nb = 0; nb < 4; ++nb) {
                mma_bf16(acc[2 * nb],     ah, BL[nb][0], BL[nb][1]);
                mma_bf16(acc[2 * nb + 1], ah, BL[nb][2], BL[nb][3]);
            }
        }
        __syncthreads();
    }

    const int m1 = wid * 16 + (lane >> 2);

    if (which < 2) {
        unsigned short* Gh = which ? g_Kh : g_Qh;
        unsigned short* Gl = which ? g_Kl : g_Ql;
#pragma unroll
        for (int j = 0; j < 8; ++j) {
            int co = j * 8 + (lane & 3) * 2;
            float b0 = bias[co0 + co], b1 = bias[co0 + co + 1];
            uint32_t h01, l01, h23, l23;
            split_pack(acc[j][0] + b0, acc[j][1] + b1, h01, l01);
            split_pack(acc[j][2] + b0, acc[j][3] + b1, h23, l23);
            size_t e1 = ((size_t)b * Nn + n0 + m1) * Cc + co0 + co;
            size_t e2 = e1 + 8 * (size_t)Cc;
            *(uint32_t*)(Gh + e1) = h01;
            *(uint32_t*)(Gl + e1) = l01;
            *(uint32_t*)(Gh + e2) = h23;
            *(uint32_t*)(Gl + e2) = l23;
        }
    } else {
        float* stage = (float*)psm;     // [co 64][m 68]
#pragma unroll
        for (int j = 0; j < 8; ++j) {
            int co = j * 8 + (lane & 3) * 2;
            float b0 = bias[co0 + co], b1 = bias[co0 + co + 1];
            stage[co * 68 + m1]           = acc[j][0] + b0;
            stage[(co + 1) * 68 + m1]     = acc[j][1] + b1;
            stage[co * 68 + m1 + 8]       = acc[j][2] + b0;
            stage[(co + 1) * 68 + m1 + 8] = acc[j][3] + b1;
        }
        __syncthreads();
#pragma unroll
        for (int l = tid; l < 2048; l += 128) {
            int co = l >> 5, mp = (l & 31) * 2;
            float v0 = stage[co * 68 + mp], v1 = stage[co * 68 + mp + 1];
            size_t e = ((size_t)b * Cc + co0 + co) * Nn + n0 + mp;
            *(uint32_t*)(g_Vt + e) = pack_h2(v0, v1);
        }
    }
}

// ---------------------------------------------------------------------------
// HMMA flash attention: TWO INDEPENDENT 128-thread groups (named barriers).
// Group g handles tiles t≡g (mod 2) of 64 keys; own double buffer; own
// online-softmax stats; merged in epilogue. bf16x3 S, fp16x1 PV.
// Chunk = 64 keys x 64 ch (K hi+lo 9216B each; V fp16 8192B), pitch 72 b16.
// ---------------------------------------------------------------------------
#define SM_QH  256
#define SM_QL  (SM_QH + 33792)            // 34048
#define SM_BUF (SM_QL + 33792)            // 67840: 4 x 18432 (grp x parity)
#define SM_STATS (SM_BUF + 4 * 18432)     // 141568: 384 floats
#define ATTN_SMEM (SM_STATS + 1664)       // 143232

__global__ __launch_bounds__(256, 1) void attn_kernel(float* __restrict__ out)
{
    extern __shared__ char smem[];
    const uint32_t sbase = smem_u32(smem);

    const int tid  = threadIdx.x;
    const int wid  = tid >> 5;
    const int lane = tid & 31;
    const int ltid = tid & 127;       // tid within group
    const int grp  = tid >> 7;        // 0 / 1
    const int b    = blockIdx.y;
    const int m0   = blockIdx.x * BM;

    const int wm = (wid & 3) * 16;    // warp row block (same for both groups)

    const int arow   = wm + (lane & 7) + ((lane >> 3) & 1) * 8;
    const int ak     = (lane >> 4) * 8;
    const int bn_row = (lane & 7) + (lane >> 4) * 8;
    const int bk_add = ((lane >> 3) & 1) * 8;

    const uint32_t qbH = sbase + SM_QH, qbL = sbase + SM_QL;

    // group's chunk buffers (parity = chunk index & 1)
    auto buf_base = [&](int parity) -> uint32_t {
        return sbase + SM_BUF + (uint32_t)(grp * 2 + parity) * 18432u;
    };

    // issue chunk ci (0..143 per group): tile t = grp + (ci>>3)*2, j = ci&7
    auto issue_chunk = [&](int ci) {
        int t = grp + (ci >> 3) * 2, j = ci & 7;
        int n0 = t * TN;
        uint32_t base = buf_base(ci & 1);
        if (j < 4) {
            // K chunk: [64 keys][64 ch] hi+lo, pitch 72 b16
            const char* Gh = (const char*)g_Kh;
            const char* Gl = (const char*)g_Kl;
#pragma unroll
            for (int tt = 0; tt < 4; ++tt) {
                int l = ltid + tt * 128;
                int n = l >> 3, c8 = l & 7;
                size_t gb = (((size_t)b * Nn + n0 + n) * Cc + j * 64 + c8 * 8) * 2;
                uint32_t so = (uint32_t)((n * 72 + c8 * 8) * 2);
                cp16(base + so, Gh + gb);
                cp16(base + 9216 + so, Gl + gb);
            }
        } else {
            // V chunk: [64 ch][64 keys] fp16, pitch 72 b16
            int vc = j - 4;
            const char* Gv = (const char*)g_Vt;
#pragma unroll
            for (int tt = 0; tt < 4; ++tt) {
                int l = ltid + tt * 128;
                int c = l >> 3, k8 = l & 7;
                size_t gb = (((size_t)b * Cc + vc * 64 + c) * Nn + n0 + k8 * 8) * 2;
                uint32_t so = (uint32_t)((c * 72 + k8 * 8) * 2);
                cp16(base + so, Gv + gb);
            }
        }
    };

    issue_chunk(0);
    CP_COMMIT();

    // ---- load Q tile hi/lo (all 256 threads) ----
    {
        const uint4* Gh = (const uint4*)g_Qh;
        const uint4* Gl = (const uint4*)g_Ql;
        uint4* Dh = (uint4*)(smem + SM_QH);
        uint4* Dl = (uint4*)(smem + SM_QL);
#pragma unroll
        for (int l = tid; l < 2048; l += 256) {
            int m = l >> 5, c8 = l & 31;
            size_t gi = (((size_t)b * Nn + m0 + m) * Cc + c8 * 8) >> 3;
            int d = m * 33 + c8;
            Dh[d] = Gh[gi];
            Dl[d] = Gl[gi];
        }
    }
    __syncthreads();   // Q visible to all; groups now fully independent

    float oacc[32][4];                     // 16 rows x 256 ch
#pragma unroll
    for (int f = 0; f < 32; f++)
#pragma unroll
        for (int e = 0; e < 4; e++) oacc[f][e] = 0.f;

    float sacc[8][4];
    uint32_t pF01[8], pF23[8];
    float s0 = 0.f, s1 = 0.f;
    float m_a = -1e30f, m_b = -1e30f;

    const int NCH = (NT / 2) * 8;          // 144 chunks per group
    const int bar_id = grp + 1;

    for (int ci = 0; ci < NCH; ++ci) {
        const int j = ci & 7;
        CP_WAIT0();
        GBAR(bar_id);                       // chunk ci visible to group
        if (ci + 1 < NCH) issue_chunk(ci + 1);
        CP_COMMIT();

        const uint32_t bB = buf_base(ci & 1);

        if (j < 4) {
            // ------------- S += Q K^T (channel chunk j), bf16x3 -------------
            const int cc = j;
            if (j == 0) {
#pragma unroll
                for (int f = 0; f < 8; f++)
#pragma unroll
                    for (int e = 0; e < 4; e++) sacc[f][e] = 0.f;
            }
#pragma unroll
            for (int ks = 0; ks < 4; ++ks) {
                const int k0 = ks * 16;
                uint32_t qh[4], ql[4];
                uint32_t qa = (uint32_t)((arow * 264 + cc * 64 + k0 + ak) * 2);
                LDSM4(qh, qbH + qa);
                LDSM4(ql, qbL + qa);
                uint32_t BH[4][4], BL[4][4];
#pragma unroll
                for (int nb = 0; nb < 4; ++nb) {
                    uint32_t kaddr = (uint32_t)(((nb * 16 + bn_row) * 72 + k0 + bk_add) * 2);
                    LDSM4(BH[nb], bB + kaddr);
                    LDSM4(BL[nb], bB + 9216 + kaddr);
                }
#pragma unroll
                for (int nb = 0; nb < 4; ++nb) {
                    mma_bf16(sacc[2 * nb],     qh, BH[nb][0], BH[nb][1]);
                    mma_bf16(sacc[2 * nb + 1], qh, BH[nb][2], BH[nb][3]);
                }
#pragma unroll
                for (int nb = 0; nb < 4; ++nb) {
                    mma_bf16(sacc[2 * nb],     ql, BH[nb][0], BH[nb][1]);
                    mma_bf16(sacc[2 * nb + 1], ql, BH[nb][2], BH[nb][3]);
                }
#pragma unroll
                for (int nb = 0; nb < 4; ++nb) {
                    mma_bf16(sacc[2 * nb],     qh, BL[nb][0], BL[nb][1]);
                    mma_bf16(sacc[2 * nb + 1], qh, BL[nb][2], BL[nb][3]);
                }
            }
            if (j == 3) {
                // ---- online softmax (per group), fp16 P pack ----
                float ma = -1e30f, mb = -1e30f;
#pragma unroll
                for (int f = 0; f < 8; ++f) {
                    ma = fmaxf(ma, fmaxf(sacc[f][0], sacc[f][1]));
                    mb = fmaxf(mb, fmaxf(sacc[f][2], sacc[f][3]));
                }
                ma = fmaxf(ma, __shfl_xor_sync(0xffffffffu, ma, 1));
                ma = fmaxf(ma, __shfl_xor_sync(0xffffffffu, ma, 2));
                mb = fmaxf(mb, __shfl_xor_sync(0xffffffffu, mb, 1));
                mb = fmaxf(mb, __shfl_xor_sync(0xffffffffu, mb, 2));
                float mna = fmaxf(m_a, ma), mnb = fmaxf(m_b, mb);
                float aa = __expf(m_a - mna), ab = __expf(m_b - mnb);
                m_a = mna; m_b = mnb;
                s0 *= aa; s1 *= ab;
#pragma unroll
                for (int f = 0; f < 8; ++f) {
                    float p0 = __expf(sacc[f][0] - m_a);
                    float p1 = __expf(sacc[f][1] - m_a);
                    float p2 = __expf(sacc[f][2] - m_b);
                    float p3 = __expf(sacc[f][3] - m_b);
                    s0 += p0 + p1;
                    s1 += p2 + p3;
                    pF01[f] = pack_h2(p0, p1);
                    pF23[f] = pack_h2(p2, p3);
                }
#pragma unroll
                for (int f = 0; f < 32; ++f) {
                    oacc[f][0] *= aa; oacc[f][1] *= aa;
                    oacc[f][2] *= ab; oacc[f][3] *= ab;
                }
            }
        } else {
            // ------------- O += P V (channel chunk j-4), fp16x1 -------------
            const int vc = j - 4;
#pragma unroll
            for (int ks = 0; ks < 4; ++ks) {
                const int k0 = ks * 16;
                uint32_t paf[4] = {pF01[2 * ks], pF23[2 * ks],
                                   pF01[2 * ks + 1], pF23[2 * ks + 1]};
#pragma unroll
                for (int g2 = 0; g2 < 2; ++g2) {
                    uint32_t VH0[4], VH1[4];
                    uint32_t va0 = (uint32_t)((((2 * g2) * 16 + bn_row) * 72 + k0 + bk_add) * 2);
                    uint32_t va1 = (uint32_t)((((2 * g2 + 1) * 16 + bn_row) * 72 + k0 + bk_add) * 2);
                    LDSM4(VH0, bB + va0);
                    LDSM4(VH1, bB + va1);
                    mma_fp16(oacc[vc * 8 + g2 * 4],     paf, VH0[0], VH0[1]);
                    mma_fp16(oacc[vc * 8 + g2 * 4 + 1], paf, VH0[2], VH0[3]);
                    mma_fp16(oacc[vc * 8 + g2 * 4 + 2], paf, VH1[0], VH1[1]);
                    mma_fp16(oacc[vc * 8 + g2 * 4 + 3], paf, VH1[2], VH1[3]);
                }
            }
        }
    }

    // ================ epilogue: merge groups with max factors ============
    __syncthreads();
    s0 += __shfl_xor_sync(0xffffffffu, s0, 1);
    s0 += __shfl_xor_sync(0xffffffffu, s0, 2);
    s1 += __shfl_xor_sync(0xffffffffu, s1, 1);
    s1 += __shfl_xor_sync(0xffffffffu, s1, 2);

    float* m_sm  = (float*)(smem + SM_STATS);        // [128]
    float* rs_sm = m_sm + 128;                       // [128]
    float* g0_sm = rs_sm + 128;                      // [64]
    float* g1_sm = g0_sm + 64;                       // [64]
    const int r = wm + (lane >> 2);
    if ((lane & 3) == 0) {
        m_sm[grp * 64 + r]      = m_a;
        rs_sm[grp * 64 + r]     = s0;
        m_sm[grp * 64 + r + 8]  = m_b;
        rs_sm[grp * 64 + r + 8] = s1;
    }
    __syncthreads();
    if (tid < 64) {
        float m0v = m_sm[tid], m1v = m_sm[64 + tid];
        float r0 = rs_sm[tid], r1 = rs_sm[64 + tid];
        float REF = fmaxf(m0v, m1v);
        float f0 = __expf(m0v - REF), f1 = __expf(m1v - REF);
        float inv = 1.f / (f0 * r0 + f1 * r1);
        g0_sm[tid] = f0 * inv;
        g1_sm[tid] = f1 * inv;
    }
    __syncthreads();

    float* st1 = (float*)(smem + SM_QH);     // [64 rows][pitch 260]
    if (grp == 1) {
        float ga = g1_sm[r], gb = g1_sm[r + 8];
#pragma unroll
        for (int q = 0; q < 32; ++q) {
            int ch = q * 8 + (lane & 3) * 2;
            st1[r * 260 + ch]           = oacc[q][0] * ga;
            st1[r * 260 + ch + 1]       = oacc[q][1] * ga;
            st1[(r + 8) * 260 + ch]     = oacc[q][2] * gb;
            st1[(r + 8) * 260 + ch + 1] = oacc[q][3] * gb;
        }
    }
    __syncthreads();
    float* st2 = (float*)(smem + SM_BUF);    // [256 ch][pitch 68]
    if (grp == 0) {
        float ga = g0_sm[r], gb = g0_sm[r + 8];
#pragma unroll
        for (int q = 0; q < 32; ++q) {
            int ch = q * 8 + (lane & 3) * 2;
            st2[ch * 68 + r]           = oacc[q][0] * ga + st1[r * 260 + ch];
            st2[(ch + 1) * 68 + r]     = oacc[q][1] * ga + st1[r * 260 + ch + 1];
            st2[ch * 68 + r + 8]       = oacc[q][2] * gb + st1[(r + 8) * 260 + ch];
            st2[(ch + 1) * 68 + r + 8] = oacc[q][3] * gb + st1[(r + 8) * 260 + ch + 1];
        }
    }
    __syncthreads();
    float* outb = out + (size_t)b * Cc * Nn;
#pragma unroll
    for (int l = tid; l < 16384; l += 256) {
        int ch = l >> 6, m = l & 63;
        outb[(size_t)ch * Nn + m0 + m] = st2[ch * 68 + m];
    }
}

// ---------------------------------------------------------------------------
extern "C" void kernel_launch(void* const* d_in, const int* in_sizes, int n_in,
                              void* d_out, int out_size)
{
    (void)in_sizes; (void)n_in; (void)out_size;
    const float* x  = (const float*)d_in[0];
    const float* y  = (const float*)d_in[1];
    const float* Wq = (const float*)d_in[2];
    const float* bq = (const float*)d_in[3];
    const float* Wk = (const float*)d_in[4];
    const float* bk = (const float*)d_in[5];
    const float* Wv = (const float*)d_in[6];
    const float* bv = (const float*)d_in[7];
    float* out = (float*)d_out;

    prep_xy<<<dim3(2304, 1, 2), 256>>>((const float4*)x, (const float4*)y);
    prep_w<<<dim3(64, 1, 3), 256>>>((const float4*)Wq, (const float4*)Wk,
                                    (const float4*)Wv);
    proj_hmma<<<dim3(Nn / 64, Cc / 64, 24), 128>>>(bq, bk, bv);

    cudaFuncSetAttribute(attn_kernel,
                         cudaFuncAttributeMaxDynamicSharedMemorySize, ATTN_SMEM);
    dim3 ag(Nn / BM, Bb);
    attn_kernel<<<ag, 256, ATTN_SMEM>>>(out);
}

// round 13
// speedup vs baseline: 1.1663x; 1.0180x over previous
#include <cuda_runtime.h>
#include <cuda_bf16.h>
#include <cuda_fp16.h>
#include <math.h>
#include <stdint.h>

#define Bb 8
#define Cc 256
#define Nn 2304
#define BM 64
#define TN 64             // keys per tile
#define NT (Nn / TN)      // 36 tiles, split even/odd between groups

// ---------------- global scratch ----------------
__device__ __align__(16) unsigned short g_Qh[(size_t)Bb * Nn * Cc];   // bf16 hi
__device__ __align__(16) unsigned short g_Ql[(size_t)Bb * Nn * Cc];   // bf16 lo
__device__ __align__(16) unsigned short g_Kh[(size_t)Bb * Nn * Cc];   // bf16 hi
__device__ __align__(16) unsigned short g_Kl[(size_t)Bb * Nn * Cc];   // bf16 lo
__device__ __align__(16) unsigned short g_Vt[(size_t)Bb * Cc * Nn];   // fp16, channel-major
// inputs split to bf16 hi/lo (channel-major, same layout as x/y)
__device__ __align__(16) unsigned short g_Xh[(size_t)Bb * Cc * Nn];
__device__ __align__(16) unsigned short g_Xl[(size_t)Bb * Cc * Nn];
__device__ __align__(16) unsigned short g_Yh[(size_t)Bb * Cc * Nn];
__device__ __align__(16) unsigned short g_Yl[(size_t)Bb * Cc * Nn];
// weights split ([co][ci], row-major)
__device__ __align__(16) unsigned short g_Wh[3][Cc * Cc];
__device__ __align__(16) unsigned short g_Wl[3][Cc * Cc];

// ---------------- helpers ----------------
__device__ __forceinline__ uint32_t smem_u32(const void* p) {
    uint32_t a;
    asm("{ .reg .u64 t; cvta.to.shared.u64 t, %1; cvt.u32.u64 %0, t; }" : "=r"(a) : "l"(p));
    return a;
}

#define LDSM4(r, addr) \
    asm volatile("ldmatrix.sync.aligned.m8n8.x4.shared.b16 {%0,%1,%2,%3}, [%4];" \
        : "=r"((r)[0]), "=r"((r)[1]), "=r"((r)[2]), "=r"((r)[3]) : "r"(addr))
#define LDSM4T(r, addr) \
    asm volatile("ldmatrix.sync.aligned.m8n8.x4.trans.shared.b16 {%0,%1,%2,%3}, [%4];" \
        : "=r"((r)[0]), "=r"((r)[1]), "=r"((r)[2]), "=r"((r)[3]) : "r"(addr))

#define GBAR(id) asm volatile("bar.sync %0, 128;" :: "r"(id) : "memory")

__device__ __forceinline__ void mma_bf16(float* c, const uint32_t* a,
                                         uint32_t b0, uint32_t b1) {
    asm volatile(
        "mma.sync.aligned.m16n8k16.row.col.f32.bf16.bf16.f32 "
        "{%0,%1,%2,%3}, {%4,%5,%6,%7}, {%8,%9}, {%0,%1,%2,%3};"
        : "+f"(c[0]), "+f"(c[1]), "+f"(c[2]), "+f"(c[3])
        : "r"(a[0]), "r"(a[1]), "r"(a[2]), "r"(a[3]), "r"(b0), "r"(b1));
}

__device__ __forceinline__ void mma_fp16(float* c, const uint32_t* a,
                                         uint32_t b0, uint32_t b1) {
    asm volatile(
        "mma.sync.aligned.m16n8k16.row.col.f32.f16.f16.f32 "
        "{%0,%1,%2,%3}, {%4,%5,%6,%7}, {%8,%9}, {%0,%1,%2,%3};"
        : "+f"(c[0]), "+f"(c[1]), "+f"(c[2]), "+f"(c[3])
        : "r"(a[0]), "r"(a[1]), "r"(a[2]), "r"(a[3]), "r"(b0), "r"(b1));
}

__device__ __forceinline__ void cp16(uint32_t s, const void* g) {
    asm volatile("cp.async.cg.shared.global [%0], [%1], 16;" :: "r"(s), "l"(g) : "memory");
}
#define CP_COMMIT() asm volatile("cp.async.commit_group;" ::: "memory")
#define CP_WAIT0()  asm volatile("cp.async.wait_group 0;" ::: "memory")
#define CP_WAIT2()  asm volatile("cp.async.wait_group 2;" ::: "memory")

__device__ __forceinline__ void split2(float v, unsigned short& h, unsigned short& l) {
    __nv_bfloat16 bh = __float2bfloat16(v);
    float r = v - __bfloat162float(bh);
    h = __bfloat16_as_ushort(bh);
    l = __bfloat16_as_ushort(__float2bfloat16(r));
}

__device__ __forceinline__ void split_pack(float a, float b, uint32_t& h, uint32_t& l) {
    unsigned short ah, al, bh, bl;
    split2(a, ah, al);
    split2(b, bh, bl);
    h = (uint32_t)ah | ((uint32_t)bh << 16);
    l = (uint32_t)al | ((uint32_t)bl << 16);
}

__device__ __forceinline__ uint32_t pack_h2(float a, float b) {
    __half2 h = __floats2half2_rn(a, b);
    return *(uint32_t*)&h;
}

// ---------------------------------------------------------------------------
// Prep: split x,y (fp32) -> bf16 hi/lo. grid (2304,1,2) x 256
// ---------------------------------------------------------------------------
__global__ __launch_bounds__(256) void prep_xy(const float4* __restrict__ x,
                                               const float4* __restrict__ y)
{
    const int z = blockIdx.z;
    const float4* src = z ? y : x;
    uint4* H = (uint4*)(z ? g_Yh : g_Xh);
    uint4* L = (uint4*)(z ? g_Yl : g_Xl);
    size_t i = (size_t)blockIdx.x * 512 + threadIdx.x * 2;
    float4 f0 = src[i], f1 = src[i + 1];
    uint4 h, l;
    split_pack(f0.x, f0.y, h.x, l.x);
    split_pack(f0.z, f0.w, h.y, l.y);
    split_pack(f1.x, f1.y, h.z, l.z);
    split_pack(f1.z, f1.w, h.w, l.w);
    H[i >> 1] = h;
    L[i >> 1] = l;
}

// Prep: split Wq/Wk/Wv. grid (64,1,3) x 256
__global__ __launch_bounds__(256) void prep_w(const float4* __restrict__ Wq,
                                              const float4* __restrict__ Wk,
                                              const float4* __restrict__ Wv)
{
    const int z = blockIdx.z;
    const float4* src = (z == 0) ? Wq : ((z == 1) ? Wk : Wv);
    uint2* H = (uint2*)g_Wh[z];
    uint2* L = (uint2*)g_Wl[z];
    int i = blockIdx.x * 256 + threadIdx.x;
    float4 f = src[i];
    uint2 h, l;
    split_pack(f.x, f.y, h.x, l.x);
    split_pack(f.z, f.w, h.y, l.y);
    H[i] = h;
    L[i] = l;
}

// ---------------------------------------------------------------------------
// HMMA projections (bf16x3): 64tok x 64co per CTA, 128 threads (4 warps).
// ---------------------------------------------------------------------------
#define PX_H 0
#define PX_L 9216
#define PW_H 18432
#define PW_L 27648

__global__ __launch_bounds__(128) void proj_hmma(
    const float* __restrict__ bq, const float* __restrict__ bk,
    const float* __restrict__ bv)
{
    __shared__ char psm[36864];
    const uint32_t sb = smem_u32(psm);

    const int tid  = threadIdx.x;
    const int wid  = tid >> 5;
    const int lane = tid & 31;
    const int n0    = blockIdx.x * 64;
    const int co0   = blockIdx.y * 64;
    const int which = blockIdx.z >> 3;
    const int b     = blockIdx.z & 7;

    const unsigned short* Xh = (which == 0) ? g_Xh : g_Yh;
    const unsigned short* Xl = (which == 0) ? g_Xl : g_Yl;
    const unsigned short* Wh = g_Wh[which];
    const unsigned short* Wl = g_Wl[which];
    const float* bias = (which == 0) ? bq : ((which == 1) ? bk : bv);

    const int a_ci = (lane & 7) + ((lane >> 4) & 1) * 8;
    const int a_m  = wid * 16 + ((lane >> 3) & 1) * 8;
    const int b_row = (lane & 7) + (lane >> 4) * 8;
    const int b_k   = ((lane >> 3) & 1) * 8;

    float acc[8][4];
#pragma unroll
    for (int j = 0; j < 8; j++)
#pragma unroll
        for (int e = 0; e < 4; e++) acc[j][e] = 0.f;

    for (int ck = 0; ck < 4; ++ck) {
#pragma unroll
        for (int t = 0; t < 4; ++t) {
            int l = tid + t * 128;
            int r = l >> 3, s = l & 7;
            size_t xg = (((size_t)b * Cc + ck * 64 + r) * Nn + n0 + s * 8) * 2;
            uint32_t xo = (uint32_t)(r * 144 + s * 16);
            cp16(sb + PX_H + xo, (const char*)Xh + xg);
            cp16(sb + PX_L + xo, (const char*)Xl + xg);
            size_t wg = (size_t)((co0 + r) * Cc + ck * 64 + s * 8) * 2;
            cp16(sb + PW_H + xo, (const char*)Wh + wg);
            cp16(sb + PW_L + xo, (const char*)Wl + wg);
        }
        CP_COMMIT();
        CP_WAIT0();
        __syncthreads();

#pragma unroll
        for (int ks = 0; ks < 4; ++ks) {
            uint32_t ah[4], al4[4];
            uint32_t aa = (uint32_t)((ks * 16 + a_ci) * 144 + a_m * 2);
            LDSM4T(ah, sb + PX_H + aa);
            LDSM4T(al4, sb + PX_L + aa);
            uint32_t BH[4][4], BL[4][4];
#pragma unroll
            for (int nb = 0; nb < 4; ++nb) {
                uint32_t ba = (uint32_t)((nb * 16 + b_row) * 144 + (ks * 16 + b_k) * 2);
                LDSM4(BH[nb], sb + PW_H + ba);
                LDSM4(BL[nb], sb + PW_L + ba);
            }
#pragma unroll
            for (int nb = 0; nb < 4; ++nb) {
                mma_bf16(acc[2 * nb],     ah, BH[nb][0], BH[nb][1]);
                mma_bf16(acc[2 * nb + 1], ah, BH[nb][2], BH[nb][3]);
            }
#pragma unroll
            for (int nb = 0; nb < 4; ++nb) {
                mma_bf16(acc[2 * nb],     al4, BH[nb][0], BH[nb][1]);
                mma_bf16(acc[2 * nb + 1], al4, BH[nb][2], BH[nb][3]);
            }
#pragma unroll
            for (int nb = 0; nb < 4; ++nb) {
                mma_bf16(acc[2 * nb],     ah, BL[nb][0], BL[nb][1]);
                mma_bf16(acc[2 * nb + 1], ah, BL[nb][2], BL[nb][3]);
            }
        }
        __syncthreads();
    }

    const int m1 = wid * 16 + (lane >> 2);

    if (which < 2) {
        unsigned short* Gh = which ? g_Kh : g_Qh;
        unsigned short* Gl = which ? g_Kl : g_Ql;
#pragma unroll
        for (int j = 0; j < 8; ++j) {
            int co = j * 8 + (lane & 3) * 2;
            float b0 = bias[co0 + co], b1 = bias[co0 + co + 1];
            uint32_t h01, l01, h23, l23;
            split_pack(acc[j][0] + b0, acc[j][1] + b1, h01, l01);
            split_pack(acc[j][2] + b0, acc[j][3] + b1, h23, l23);
            size_t e1 = ((size_t)b * Nn + n0 + m1) * Cc + co0 + co;
            size_t e2 = e1 + 8 * (size_t)Cc;
            *(uint32_t*)(Gh + e1) = h01;
            *(uint32_t*)(Gl + e1) = l01;
            *(uint32_t*)(Gh + e2) = h23;
            *(uint32_t*)(Gl + e2) = l23;
        }
    } else {
        float* stage = (float*)psm;     // [co 64][m 68]
#pragma unroll
        for (int j = 0; j < 8; ++j) {
            int co = j * 8 + (lane & 3) * 2;
            float b0 = bias[co0 + co], b1 = bias[co0 + co + 1];
            stage[co * 68 + m1]           = acc[j][0] + b0;
            stage[(co + 1) * 68 + m1]     = acc[j][1] + b1;
            stage[co * 68 + m1 + 8]       = acc[j][2] + b0;
            stage[(co + 1) * 68 + m1 + 8] = acc[j][3] + b1;
        }
        __syncthreads();
#pragma unroll
        for (int l = tid; l < 2048; l += 128) {
            int co = l >> 5, mp = (l & 31) * 2;
            float v0 = stage[co * 68 + mp], v1 = stage[co * 68 + mp + 1];
            size_t e = ((size_t)b * Cc + co0 + co) * Nn + n0 + mp;
            *(uint32_t*)(g_Vt + e) = pack_h2(v0, v1);
        }
    }
}

// ---------------------------------------------------------------------------
// HMMA flash attention: two independent 128-thread groups (named barriers),
// 4-deep cp.async pipeline per group (1 barrier/chunk, lookahead 2-3),
// guarded O-rescale. bf16x3 S, fp16x1 PV.
// Chunk = 64 keys x 64 ch (K hi+lo 9216B each; V fp16 9216 slot), pitch 72 b16.
// ---------------------------------------------------------------------------
#define SM_QH  256
#define SM_QL  (SM_QH + 33792)            // 34048
#define SM_BUF (SM_QL + 33792)            // 67840: 8 x 18432 (grp x slot)
#define SM_STATS (SM_BUF + 8 * 18432)     // 215296
#define ATTN_SMEM (SM_STATS + 1664)       // 216960

__global__ __launch_bounds__(256, 1) void attn_kernel(float* __restrict__ out)
{
    extern __shared__ char smem[];
    const uint32_t sbase = smem_u32(smem);

    const int tid  = threadIdx.x;
    const int wid  = tid >> 5;
    const int lane = tid & 31;
    const int ltid = tid & 127;       // tid within group
    const int grp  = tid >> 7;        // 0 / 1
    const int b    = blockIdx.y;
    const int m0   = blockIdx.x * BM;

    const int wm = (wid & 3) * 16;    // warp row block

    const int arow   = wm + (lane & 7) + ((lane >> 3) & 1) * 8;
    const int ak     = (lane >> 4) * 8;
    const int bn_row = (lane & 7) + (lane >> 4) * 8;
    const int bk_add = ((lane >> 3) & 1) * 8;

    const uint32_t qbH = sbase + SM_QH, qbL = sbase + SM_QL;

    // group's chunk buffers (slot = chunk index & 3)
    auto buf_base = [&](int slot) -> uint32_t {
        return sbase + SM_BUF + (uint32_t)(grp * 4 + slot) * 18432u;
    };

    // issue chunk ci (0..143 per group): tile t = grp + (ci>>3)*2, j = ci&7
    auto issue_chunk = [&](int ci) {
        int t = grp + (ci >> 3) * 2, j = ci & 7;
        int n0 = t * TN;
        uint32_t base = buf_base(ci & 3);
        if (j < 4) {
            const char* Gh = (const char*)g_Kh;
            const char* Gl = (const char*)g_Kl;
#pragma unroll
            for (int tt = 0; tt < 4; ++tt) {
                int l = ltid + tt * 128;
                int n = l >> 3, c8 = l & 7;
                size_t gb = (((size_t)b * Nn + n0 + n) * Cc + j * 64 + c8 * 8) * 2;
                uint32_t so = (uint32_t)((n * 72 + c8 * 8) * 2);
                cp16(base + so, Gh + gb);
                cp16(base + 9216 + so, Gl + gb);
            }
        } else {
            int vc = j - 4;
            const char* Gv = (const char*)g_Vt;
#pragma unroll
            for (int tt = 0; tt < 4; ++tt) {
                int l = ltid + tt * 128;
                int c = l >> 3, k8 = l & 7;
                size_t gb = (((size_t)b * Cc + vc * 64 + c) * Nn + n0 + k8 * 8) * 2;
                uint32_t so = (uint32_t)((c * 72 + k8 * 8) * 2);
                cp16(base + so, Gv + gb);
            }
        }
    };

    issue_chunk(0); CP_COMMIT();
    issue_chunk(1); CP_COMMIT();

    // ---- load Q tile hi/lo (all 256 threads) while chunks fly ----
    {
        const uint4* Gh = (const uint4*)g_Qh;
        const uint4* Gl = (const uint4*)g_Ql;
        uint4* Dh = (uint4*)(smem + SM_QH);
        uint4* Dl = (uint4*)(smem + SM_QL);
#pragma unroll
        for (int l = tid; l < 2048; l += 256) {
            int m = l >> 5, c8 = l & 31;
            size_t gi = (((size_t)b * Nn + m0 + m) * Cc + c8 * 8) >> 3;
            int d = m * 33 + c8;
            Dh[d] = Gh[gi];
            Dl[d] = Gl[gi];
        }
    }
    issue_chunk(2); CP_COMMIT();
    __syncthreads();   // Q visible to all; groups now fully independent

    float oacc[32][4];                     // 16 rows x 256 ch
#pragma unroll
    for (int f = 0; f < 32; f++)
#pragma unroll
        for (int e = 0; e < 4; e++) oacc[f][e] = 0.f;

    float sacc[8][4];
    uint32_t pF01[8], pF23[8];
    float s0 = 0.f, s1 = 0.f;
    float m_a = -1e30f, m_b = -1e30f;

    const int NCH = (NT / 2) * 8;          // 144 chunks per group
    const int bar_id = grp + 1;

    for (int ci = 0; ci < NCH; ++ci) {
        const int j = ci & 7;
        CP_WAIT2();                         // chunk ci landed (ci+1,ci+2 in flight)
        GBAR(bar_id);                       // visible to group; slot ci+3 free
        if (ci + 3 < NCH) issue_chunk(ci + 3);
        CP_COMMIT();

        const uint32_t bB = buf_base(ci & 3);

        if (j < 4) {
            // ------------- S += Q K^T (channel chunk j), bf16x3 -------------
            const int cc = j;
            if (j == 0) {
#pragma unroll
                for (int f = 0; f < 8; f++)
#pragma unroll
                    for (int e = 0; e < 4; e++) sacc[f][e] = 0.f;
            }
#pragma unroll
            for (int ks = 0; ks < 4; ++ks) {
                const int k0 = ks * 16;
                uint32_t qh[4], ql[4];
                uint32_t qa = (uint32_t)((arow * 264 + cc * 64 + k0 + ak) * 2);
                LDSM4(qh, qbH + qa);
                LDSM4(ql, qbL + qa);
                uint32_t BH[4][4], BL[4][4];
#pragma unroll
                for (int nb = 0; nb < 4; ++nb) {
                    uint32_t kaddr = (uint32_t)(((nb * 16 + bn_row) * 72 + k0 + bk_add) * 2);
                    LDSM4(BH[nb], bB + kaddr);
                    LDSM4(BL[nb], bB + 9216 + kaddr);
                }
#pragma unroll
                for (int nb = 0; nb < 4; ++nb) {
                    mma_bf16(sacc[2 * nb],     qh, BH[nb][0], BH[nb][1]);
                    mma_bf16(sacc[2 * nb + 1], qh, BH[nb][2], BH[nb][3]);
                }
#pragma unroll
                for (int nb = 0; nb < 4; ++nb) {
                    mma_bf16(sacc[2 * nb],     ql, BH[nb][0], BH[nb][1]);
                    mma_bf16(sacc[2 * nb + 1], ql, BH[nb][2], BH[nb][3]);
                }
#pragma unroll
                for (int nb = 0; nb < 4; ++nb) {
                    mma_bf16(sacc[2 * nb],     qh, BL[nb][0], BL[nb][1]);
                    mma_bf16(sacc[2 * nb + 1], qh, BL[nb][2], BL[nb][3]);
                }
            }
            if (j == 3) {
                // ---- online softmax (per group), fp16 P pack ----
                float ma = -1e30f, mb = -1e30f;
#pragma unroll
                for (int f = 0; f < 8; ++f) {
                    ma = fmaxf(ma, fmaxf(sacc[f][0], sacc[f][1]));
                    mb = fmaxf(mb, fmaxf(sacc[f][2], sacc[f][3]));
                }
                ma = fmaxf(ma, __shfl_xor_sync(0xffffffffu, ma, 1));
                ma = fmaxf(ma, __shfl_xor_sync(0xffffffffu, ma, 2));
                mb = fmaxf(mb, __shfl_xor_sync(0xffffffffu, mb, 1));
                mb = fmaxf(mb, __shfl_xor_sync(0xffffffffu, mb, 2));
                float mna = fmaxf(m_a, ma), mnb = fmaxf(m_b, mb);
                float aa = __expf(m_a - mna), ab = __expf(m_b - mnb);
                m_a = mna; m_b = mnb;
                s0 *= aa; s1 *= ab;
#pragma unroll
                for (int f = 0; f < 8; ++f) {
                    float p0 = __expf(sacc[f][0] - m_a);
                    float p1 = __expf(sacc[f][1] - m_a);
                    float p2 = __expf(sacc[f][2] - m_b);
                    float p3 = __expf(sacc[f][3] - m_b);
                    s0 += p0 + p1;
                    s1 += p2 + p3;
                    pF01[f] = pack_h2(p0, p1);
                    pF23[f] = pack_h2(p2, p3);
                }
                if (aa < 1.f || ab < 1.f) {     // skip when max unchanged
#pragma unroll
                    for (int f = 0; f < 32; ++f) {
                        oacc[f][0] *= aa; oacc[f][1] *= aa;
                        oacc[f][2] *= ab; oacc[f][3] *= ab;
                    }
                }
            }
        } else {
            // ------------- O += P V (channel chunk j-4), fp16x1 -------------
            const int vc = j - 4;
#pragma unroll
            for (int ks = 0; ks < 4; ++ks) {
                const int k0 = ks * 16;
                uint32_t paf[4] = {pF01[2 * ks], pF23[2 * ks],
                                   pF01[2 * ks + 1], pF23[2 * ks + 1]};
#pragma unroll
                for (int g2 = 0; g2 < 2; ++g2) {
                    uint32_t VH0[4], VH1[4];
                    uint32_t va0 = (uint32_t)((((2 * g2) * 16 + bn_row) * 72 + k0 + bk_add) * 2);
                    uint32_t va1 = (uint32_t)((((2 * g2 + 1) * 16 + bn_row) * 72 + k0 + bk_add) * 2);
                    LDSM4(VH0, bB + va0);
                    LDSM4(VH1, bB + va1);
                    mma_fp16(oacc[vc * 8 + g2 * 4],     paf, VH0[0], VH0[1]);
                    mma_fp16(oacc[vc * 8 + g2 * 4 + 1], paf, VH0[2], VH0[3]);
                    mma_fp16(oacc[vc * 8 + g2 * 4 + 2], paf, VH1[0], VH1[1]);
                    mma_fp16(oacc[vc * 8 + g2 * 4 + 3], paf, VH1[2], VH1[3]);
                }
            }
        }
    }

    // ================ epilogue: merge groups with max factors ============
    __syncthreads();
    s0 += __shfl_xor_sync(0xffffffffu, s0, 1);
    s0 += __shfl_xor_sync(0xffffffffu, s0, 2);
    s1 += __shfl_xor_sync(0xffffffffu, s1, 1);
    s1 += __shfl_xor_sync(0xffffffffu, s1, 2);

    float* m_sm  = (float*)(smem + SM_STATS);        // [128]
    float* rs_sm = m_sm + 128;                       // [128]
    float* g0_sm = rs_sm + 128;                      // [64]
    float* g1_sm = g0_sm + 64;                       // [64]
    const int r = wm + (lane >> 2);
    if ((lane & 3) == 0) {
        m_sm[grp * 64 + r]      = m_a;
        rs_sm[grp * 64 + r]     = s0;
        m_sm[grp * 64 + r + 8]  = m_b;
        rs_sm[grp * 64 + r + 8] = s1;
    }
    __syncthreads();
    if (tid < 64) {
        float m0v = m_sm[tid], m1v = m_sm[64 + tid];
        float r0 = rs_sm[tid], r1 = rs_sm[64 + tid];
        float REF = fmaxf(m0v, m1v);
        float f0 = __expf(m0v - REF), f1 = __expf(m1v - REF);
        float inv = 1.f / (f0 * r0 + f1 * r1);
        g0_sm[tid] = f0 * inv;
        g1_sm[tid] = f1 * inv;
    }
    __syncthreads();

    float* st1 = (float*)(smem + SM_QH);     // [64 rows][pitch 260]
    if (grp == 1) {
        float ga = g1_sm[r], gb = g1_sm[r + 8];
#pragma unroll
        for (int q = 0; q < 32; ++q) {
            int ch = q * 8 + (lane & 3) * 2;
            st1[r * 260 + ch]           = oacc[q][0] * ga;
            st1[r * 260 + ch + 1]       = oacc[q][1] * ga;
            st1[(r + 8) * 260 + ch]     = oacc[q][2] * gb;
            st1[(r + 8) * 260 + ch + 1] = oacc[q][3] * gb;
        }
    }
    __syncthreads();
    float* st2 = (float*)(smem + SM_BUF);    // [256 ch][pitch 68]
    if (grp == 0) {
        float ga = g0_sm[r], gb = g0_sm[r + 8];
#pragma unroll
        for (int q = 0; q < 32; ++q) {
            int ch = q * 8 + (lane & 3) * 2;
            st2[ch * 68 + r]           = oacc[q][0] * ga + st1[r * 260 + ch];
            st2[(ch + 1) * 68 + r]     = oacc[q][1] * ga + st1[r * 260 + ch + 1];
            st2[ch * 68 + r + 8]       = oacc[q][2] * gb + st1[(r + 8) * 260 + ch];
            st2[(ch + 1) * 68 + r + 8] = oacc[q][3] * gb + st1[(r + 8) * 260 + ch + 1];
        }
    }
    __syncthreads();
    float* outb = out + (size_t)b * Cc * Nn;
#pragma unroll
    for (int l = tid; l < 16384; l += 256) {
        int ch = l >> 6, m = l & 63;
        outb[(size_t)ch * Nn + m0 + m] = st2[ch * 68 + m];
    }
}

// ---------------------------------------------------------------------------
extern "C" void kernel_launch(void* const* d_in, const int* in_sizes, int n_in,
                              void* d_out, int out_size)
{
    (void)in_sizes; (void)n_in; (void)out_size;
    const float* x  = (const float*)d_in[0];
    const float* y  = (const float*)d_in[1];
    const float* Wq = (const float*)d_in[2];
    const float* bq = (const float*)d_in[3];
    const float* Wk = (const float*)d_in[4];
    const float* bk = (const float*)d_in[5];
    const float* Wv = (const float*)d_in[6];
    const float* bv = (const float*)d_in[7];
    float* out = (float*)d_out;

    prep_xy<<<dim3(2304, 1, 2), 256>>>((const float4*)x, (const float4*)y);
    prep_w<<<dim3(64, 1, 3), 256>>>((const float4*)Wq, (const float4*)Wk,
                                    (const float4*)Wv);
    proj_hmma<<<dim3(Nn / 64, Cc / 64, 24), 128>>>(bq, bk, bv);

    cudaFuncSetAttribute(attn_kernel,
                         cudaFuncAttributeMaxDynamicSharedMemorySize, ATTN_SMEM);
    dim3 ag(Nn / BM, Bb);
    attn_kernel<<<ag, 256, ATTN_SMEM>>>(out);
}